// round 6
// baseline (speedup 1.0000x reference)
#include <cuda_runtime.h>

#define NQ 8192
#define NKV 8192
#define DD 512

static constexpr float QSCALE = 0.044194173824159216f; // 1/sqrt(512)

// Scratch for projected q, k, v (16 MB each) — __device__ globals, no allocation.
__device__ float g_q[NQ * DD];
__device__ float g_k[NKV * DD];
__device__ float g_v[NKV * DD];

// ---------------------------------------------------------------------------
// Projection: O[row, col] = sum_d A[row, d] * W[col, d] + b[col]   (y = A W^T + b)
// 128x128 tile, BK=16, 256 threads, 8x8 per thread. gridDim.z selects q/k/v.
// 1/sqrt(D) folded into the q projection output.
// ---------------------------------------------------------------------------
__global__ __launch_bounds__(256) void proj_kernel(
    const float* __restrict__ x, const float* __restrict__ dom,
    const float* __restrict__ Wq, const float* __restrict__ bq,
    const float* __restrict__ Wk, const float* __restrict__ bk,
    const float* __restrict__ Wv, const float* __restrict__ bv)
{
    __shared__ float As[16][132];
    __shared__ float Bs[16][132];

    const int z = blockIdx.z;
    const float* A = (z == 0) ? x : dom;
    const float* W = (z == 0) ? Wq : (z == 1 ? Wk : Wv);
    const float* b = (z == 0) ? bq : (z == 1 ? bk : bv);
    float* O       = (z == 0) ? g_q : (z == 1 ? g_k : g_v);
    const float scale = (z == 0) ? QSCALE : 1.0f;

    const int tid = threadIdx.x;
    const int tx = tid & 15, ty = tid >> 4;
    const int rowBase = blockIdx.y * 128;
    const int colBase = blockIdx.x * 128;

    float acc[8][8];
#pragma unroll
    for (int i = 0; i < 8; ++i)
#pragma unroll
        for (int j = 0; j < 8; ++j) acc[i][j] = 0.0f;

    for (int kt = 0; kt < DD / 16; ++kt) {
        const int k0 = kt * 16;
#pragma unroll
        for (int it = 0; it < 2; ++it) {
            int idx = tid + 256 * it;          // 0..511 (128 rows x 4 float4)
            int r = idx >> 2, c4 = idx & 3;
            float4 a = *(const float4*)&A[(size_t)(rowBase + r) * DD + k0 + c4 * 4];
            As[c4 * 4 + 0][r] = a.x; As[c4 * 4 + 1][r] = a.y;
            As[c4 * 4 + 2][r] = a.z; As[c4 * 4 + 3][r] = a.w;
            float4 w = *(const float4*)&W[(size_t)(colBase + r) * DD + k0 + c4 * 4];
            Bs[c4 * 4 + 0][r] = w.x; Bs[c4 * 4 + 1][r] = w.y;
            Bs[c4 * 4 + 2][r] = w.z; Bs[c4 * 4 + 3][r] = w.w;
        }
        __syncthreads();
#pragma unroll
        for (int k = 0; k < 16; ++k) {
            float ar[8], br[8];
            *(float4*)&ar[0] = *(const float4*)&As[k][ty * 8];
            *(float4*)&ar[4] = *(const float4*)&As[k][ty * 8 + 4];
            *(float4*)&br[0] = *(const float4*)&Bs[k][tx * 8];
            *(float4*)&br[4] = *(const float4*)&Bs[k][tx * 8 + 4];
#pragma unroll
            for (int i = 0; i < 8; ++i)
#pragma unroll
                for (int j = 0; j < 8; ++j) acc[i][j] += ar[i] * br[j];
        }
        __syncthreads();
    }

#pragma unroll
    for (int i = 0; i < 8; ++i) {
        int row = rowBase + ty * 8 + i;
#pragma unroll
        for (int jj = 0; jj < 2; ++jj) {
            int col = colBase + tx * 8 + jj * 4;
            float4 r4;
            r4.x = (acc[i][jj * 4 + 0] + b[col + 0]) * scale;
            r4.y = (acc[i][jj * 4 + 1] + b[col + 1]) * scale;
            r4.z = (acc[i][jj * 4 + 2] + b[col + 2]) * scale;
            r4.w = (acc[i][jj * 4 + 3] + b[col + 3]) * scale;
            *(float4*)&O[(size_t)row * DD + col] = r4;
        }
    }
}

// ---------------------------------------------------------------------------
// Flash attention (fp32): BM=64 q-rows per CTA, BN=128 kv-rows per tile.
// 256 threads (ty=tid/16 in [0,16), tx=tid%16).
// S tile 64x128: thread owns rows ty*4+i (i<4), cols j*16+tx (j<8).
// O tile 64x512: thread owns rows ty*4+i, cols c*64+tx*4+j (c<8, j<4).
// Online softmax state (m, l) per row, replicated across the 16 tx lanes.
// ---------------------------------------------------------------------------
// smem layout (floats):
//   Qs [64 k][68]    : k-major chunk of q   (pad 64->68)
//   Ks [64 k][132]   : k-major chunk of k   (pad 128->132)
//   Ps [128 n][68]   : transposed probabilities
//   Vs [64][516]     : v chunk              (pad 512->516)
#define QS_OFF 0
#define KS_OFF (QS_OFF + 64 * 68)
#define PS_OFF (KS_OFF + 64 * 132)
#define VS_OFF (PS_OFF + 128 * 68)
#define SMEM_FLOATS (VS_OFF + 64 * 516)
#define SMEM_BYTES (SMEM_FLOATS * 4)

__global__ __launch_bounds__(256, 1) void attn_kernel(float* __restrict__ out)
{
    extern __shared__ float sm[];
    float* Qs = sm + QS_OFF;
    float* Ks = sm + KS_OFF;
    float* Ps = sm + PS_OFF;
    float* Vs = sm + VS_OFF;

    const int tid = threadIdx.x;
    const int tx = tid & 15, ty = tid >> 4;
    const int rowBase = blockIdx.x * 64;

    float o[4][32];
#pragma unroll
    for (int i = 0; i < 4; ++i)
#pragma unroll
        for (int c = 0; c < 32; ++c) o[i][c] = 0.0f;

    float m_run[4], l_run[4];
#pragma unroll
    for (int i = 0; i < 4; ++i) { m_run[i] = -3.0e38f; l_run[i] = 0.0f; }

    for (int mt = 0; mt < NKV / 128; ++mt) {
        const int nBase = mt * 128;

        float s[4][8];
#pragma unroll
        for (int i = 0; i < 4; ++i)
#pragma unroll
            for (int j = 0; j < 8; ++j) s[i][j] = 0.0f;

        // ---- S = q_tile @ k_tile^T over D=512 in chunks of 64 ----
        for (int kc = 0; kc < 8; ++kc) {
            const int k0 = kc * 64;
#pragma unroll
            for (int it = 0; it < 4; ++it) {          // Qs: 64 rows x 16 f4
                int idx = tid + 256 * it;
                int r = idx >> 4, c4 = idx & 15;
                float4 v = *(const float4*)&g_q[(size_t)(rowBase + r) * DD + k0 + c4 * 4];
                Qs[(c4 * 4 + 0) * 68 + r] = v.x; Qs[(c4 * 4 + 1) * 68 + r] = v.y;
                Qs[(c4 * 4 + 2) * 68 + r] = v.z; Qs[(c4 * 4 + 3) * 68 + r] = v.w;
            }
#pragma unroll
            for (int it = 0; it < 8; ++it) {          // Ks: 128 rows x 16 f4
                int idx = tid + 256 * it;
                int r = idx >> 4, c4 = idx & 15;
                float4 v = *(const float4*)&g_k[(size_t)(nBase + r) * DD + k0 + c4 * 4];
                Ks[(c4 * 4 + 0) * 132 + r] = v.x; Ks[(c4 * 4 + 1) * 132 + r] = v.y;
                Ks[(c4 * 4 + 2) * 132 + r] = v.z; Ks[(c4 * 4 + 3) * 132 + r] = v.w;
            }
            __syncthreads();
#pragma unroll 4
            for (int k = 0; k < 64; ++k) {
                float4 q4 = *(const float4*)&Qs[k * 68 + ty * 4];
                float kr[8];
#pragma unroll
                for (int j = 0; j < 8; ++j) kr[j] = Ks[k * 132 + j * 16 + tx];
#pragma unroll
                for (int j = 0; j < 8; ++j) {
                    s[0][j] += q4.x * kr[j];
                    s[1][j] += q4.y * kr[j];
                    s[2][j] += q4.z * kr[j];
                    s[3][j] += q4.w * kr[j];
                }
            }
            __syncthreads();
        }

        // ---- online softmax (scale already folded into q) ----
        float mx[4], rsum[4];
#pragma unroll
        for (int i = 0; i < 4; ++i) {
            mx[i] = s[i][0];
#pragma unroll
            for (int j = 1; j < 8; ++j) mx[i] = fmaxf(mx[i], s[i][j]);
        }
#pragma unroll
        for (int off = 1; off < 16; off <<= 1)
#pragma unroll
            for (int i = 0; i < 4; ++i)
                mx[i] = fmaxf(mx[i], __shfl_xor_sync(0xffffffffu, mx[i], off));

#pragma unroll
        for (int i = 0; i < 4; ++i) {
            float newm = fmaxf(m_run[i], mx[i]);
            float corr = __expf(m_run[i] - newm);
            m_run[i] = newm;
            rsum[i] = 0.0f;
#pragma unroll
            for (int j = 0; j < 8; ++j) {
                float p = __expf(s[i][j] - newm);
                s[i][j] = p;
                rsum[i] += p;
            }
            l_run[i] *= corr;
#pragma unroll
            for (int c = 0; c < 32; ++c) o[i][c] *= corr;
        }
#pragma unroll
        for (int off = 1; off < 16; off <<= 1)
#pragma unroll
            for (int i = 0; i < 4; ++i)
                rsum[i] += __shfl_xor_sync(0xffffffffu, rsum[i], off);
#pragma unroll
        for (int i = 0; i < 4; ++i) l_run[i] += rsum[i];

        // write P transposed: Ps[n][m]
#pragma unroll
        for (int j = 0; j < 8; ++j)
#pragma unroll
            for (int i = 0; i < 4; ++i)
                Ps[(j * 16 + tx) * 68 + ty * 4 + i] = s[i][j];
        __syncthreads();

        // ---- O += P @ V over the 128 kv rows, in two 64-row halves ----
        for (int h = 0; h < 2; ++h) {
#pragma unroll
            for (int it = 0; it < 32; ++it) {          // Vs: 64 rows x 128 f4
                int idx = tid + 256 * it;
                int r = idx >> 7, c4 = idx & 127;
                float4 v = *(const float4*)&g_v[(size_t)(nBase + h * 64 + r) * DD + c4 * 4];
                *(float4*)&Vs[r * 516 + c4 * 4] = v;
            }
            __syncthreads();
#pragma unroll 4
            for (int nn = 0; nn < 64; ++nn) {
                float4 p4 = *(const float4*)&Ps[(h * 64 + nn) * 68 + ty * 4];
#pragma unroll
                for (int c = 0; c < 8; ++c) {
                    float4 vv = *(const float4*)&Vs[nn * 516 + c * 64 + tx * 4];
                    o[0][c * 4 + 0] += p4.x * vv.x;
                    o[0][c * 4 + 1] += p4.x * vv.y;
                    o[0][c * 4 + 2] += p4.x * vv.z;
                    o[0][c * 4 + 3] += p4.x * vv.w;
                    o[1][c * 4 + 0] += p4.y * vv.x;
                    o[1][c * 4 + 1] += p4.y * vv.y;
                    o[1][c * 4 + 2] += p4.y * vv.z;
                    o[1][c * 4 + 3] += p4.y * vv.w;
                    o[2][c * 4 + 0] += p4.z * vv.x;
                    o[2][c * 4 + 1] += p4.z * vv.y;
                    o[2][c * 4 + 2] += p4.z * vv.z;
                    o[2][c * 4 + 3] += p4.z * vv.w;
                    o[3][c * 4 + 0] += p4.w * vv.x;
                    o[3][c * 4 + 1] += p4.w * vv.y;
                    o[3][c * 4 + 2] += p4.w * vv.z;
                    o[3][c * 4 + 3] += p4.w * vv.w;
                }
            }
            __syncthreads();
        }
    }

    // ---- epilogue: O /= l ----
#pragma unroll
    for (int i = 0; i < 4; ++i) {
        float inv = 1.0f / l_run[i];
        int row = rowBase + ty * 4 + i;
#pragma unroll
        for (int c = 0; c < 8; ++c) {
            float4 r4;
            r4.x = o[i][c * 4 + 0] * inv;
            r4.y = o[i][c * 4 + 1] * inv;
            r4.z = o[i][c * 4 + 2] * inv;
            r4.w = o[i][c * 4 + 3] * inv;
            *(float4*)&out[(size_t)row * DD + c * 64 + tx * 4] = r4;
        }
    }
}

// ---------------------------------------------------------------------------
extern "C" void kernel_launch(void* const* d_in, const int* in_sizes, int n_in,
                              void* d_out, int out_size)
{
    const float* x   = (const float*)d_in[0];
    const float* dom = (const float*)d_in[1];
    const float* Wq  = (const float*)d_in[2];
    const float* bq  = (const float*)d_in[3];
    const float* Wk  = (const float*)d_in[4];
    const float* bk  = (const float*)d_in[5];
    const float* Wv  = (const float*)d_in[6];
    const float* bv  = (const float*)d_in[7];
    float* out = (float*)d_out;

    dim3 gproj(DD / 128, NQ / 128, 3);
    proj_kernel<<<gproj, 256>>>(x, dom, Wq, bq, Wk, bk, Wv, bv);

    cudaFuncSetAttribute(attn_kernel, cudaFuncAttributeMaxDynamicSharedMemorySize,
                         SMEM_BYTES);
    attn_kernel<<<NQ / 64, 256, SMEM_BYTES>>>(out);
}

// round 8
// speedup vs baseline: 3.1559x; 3.1559x over previous
#include <cuda_runtime.h>
#include <cuda_bf16.h>
#include <cstdint>

#define NQ 8192
#define NKV 8192
#define DDIM 512
static constexpr float QSCALE = 0.044194173824159216f; // 1/sqrt(512)

// ---------------- scratch (device globals; no allocation) ----------------
__device__ __align__(256) __nv_bfloat16 g_qh[NQ * DDIM];
__device__ __align__(256) __nv_bfloat16 g_ql[NQ * DDIM];
__device__ __align__(256) __nv_bfloat16 g_kh[NKV * DDIM];
__device__ __align__(256) __nv_bfloat16 g_kl[NKV * DDIM];
__device__ __align__(256) __nv_bfloat16 g_vth[DDIM * NKV];  // V^T [512, 8192]
__device__ __align__(256) __nv_bfloat16 g_vtl[DDIM * NKV];
__device__ __align__(256) __nv_bfloat16 g_ph[(size_t)NQ * NKV];  // P hi
__device__ __align__(256) __nv_bfloat16 g_pl[(size_t)NQ * NKV];  // P lo
__device__ float g_lpart[128 * NQ];   // [slot][row]
__device__ float g_linv[NQ];

// ---------------- helpers ----------------
__device__ __forceinline__ uint32_t smem_u32(const void* p) {
    uint32_t a;
    asm("{ .reg .u64 t; cvta.to.shared.u64 t, %1; cvt.u32.u64 %0, t; }"
        : "=r"(a) : "l"(p));
    return a;
}

#define CP16(sa, gp) \
    asm volatile("cp.async.cg.shared.global [%0], [%1], 16;" \
                 :: "r"(sa), "l"(gp) : "memory")
#define CP_COMMIT asm volatile("cp.async.commit_group;" ::: "memory")
#define CP_WAIT1  asm volatile("cp.async.wait_group 1;" ::: "memory")
#define CP_WAIT0  asm volatile("cp.async.wait_group 0;" ::: "memory")

#define LDSM_X4(r0, r1, r2, r3, addr) \
    asm volatile("ldmatrix.sync.aligned.m8n8.x4.shared.b16 {%0,%1,%2,%3}, [%4];" \
                 : "=r"(r0), "=r"(r1), "=r"(r2), "=r"(r3) : "r"(addr))

#define MMA16816(d, a, b) \
    asm volatile("mma.sync.aligned.m16n8k16.row.col.f32.bf16.bf16.f32 " \
                 "{%0,%1,%2,%3}, {%4,%5,%6,%7}, {%8,%9}, {%0,%1,%2,%3};" \
                 : "+f"((d)[0]), "+f"((d)[1]), "+f"((d)[2]), "+f"((d)[3]) \
                 : "r"((a)[0]), "r"((a)[1]), "r"((a)[2]), "r"((a)[3]), \
                   "r"((b)[0]), "r"((b)[1]))

__device__ __forceinline__ void split_bf16(float x, __nv_bfloat16& h, __nv_bfloat16& l) {
    h = __float2bfloat16(x);
    l = __float2bfloat16(x - __bfloat162float(h));
}

// ---------------------------------------------------------------------------
// Projection (fp32 FFMA, 128x128 tile) -> writes split-bf16 q, k, and V^T.
// ---------------------------------------------------------------------------
__global__ __launch_bounds__(256) void proj_kernel(
    const float* __restrict__ x, const float* __restrict__ dom,
    const float* __restrict__ Wq, const float* __restrict__ bq,
    const float* __restrict__ Wk, const float* __restrict__ bk,
    const float* __restrict__ Wv, const float* __restrict__ bv)
{
    __shared__ float As[16][132];
    __shared__ float Bs[16][132];

    const int z = blockIdx.z;
    const float* A = (z == 0) ? x : dom;
    const float* W = (z == 0) ? Wq : (z == 1 ? Wk : Wv);
    const float* b = (z == 0) ? bq : (z == 1 ? bk : bv);
    const float scale = (z == 0) ? QSCALE : 1.0f;

    const int tid = threadIdx.x;
    const int tx = tid & 15, ty = tid >> 4;
    const int rowBase = blockIdx.y * 128;
    const int colBase = blockIdx.x * 128;

    float acc[8][8];
#pragma unroll
    for (int i = 0; i < 8; ++i)
#pragma unroll
        for (int j = 0; j < 8; ++j) acc[i][j] = 0.0f;

    for (int kt = 0; kt < DDIM / 16; ++kt) {
        const int k0 = kt * 16;
#pragma unroll
        for (int it = 0; it < 2; ++it) {
            int idx = tid + 256 * it;
            int r = idx >> 2, c4 = idx & 3;
            float4 a = *(const float4*)&A[(size_t)(rowBase + r) * DDIM + k0 + c4 * 4];
            As[c4 * 4 + 0][r] = a.x; As[c4 * 4 + 1][r] = a.y;
            As[c4 * 4 + 2][r] = a.z; As[c4 * 4 + 3][r] = a.w;
            float4 w = *(const float4*)&W[(size_t)(colBase + r) * DDIM + k0 + c4 * 4];
            Bs[c4 * 4 + 0][r] = w.x; Bs[c4 * 4 + 1][r] = w.y;
            Bs[c4 * 4 + 2][r] = w.z; Bs[c4 * 4 + 3][r] = w.w;
        }
        __syncthreads();
#pragma unroll
        for (int k = 0; k < 16; ++k) {
            float ar[8], br[8];
            *(float4*)&ar[0] = *(const float4*)&As[k][ty * 8];
            *(float4*)&ar[4] = *(const float4*)&As[k][ty * 8 + 4];
            *(float4*)&br[0] = *(const float4*)&Bs[k][tx * 8];
            *(float4*)&br[4] = *(const float4*)&Bs[k][tx * 8 + 4];
#pragma unroll
            for (int i = 0; i < 8; ++i)
#pragma unroll
                for (int j = 0; j < 8; ++j) acc[i][j] += ar[i] * br[j];
        }
        __syncthreads();
    }

    if (z == 2) {
        // V^T split-bf16: vt[col][row], rows contiguous
#pragma unroll
        for (int j = 0; j < 8; ++j) {
            int col = colBase + tx * 8 + j;
            float bias = b[col];
            __align__(16) __nv_bfloat16 hb[8], lb[8];
#pragma unroll
            for (int i = 0; i < 8; ++i) split_bf16(acc[i][j] + bias, hb[i], lb[i]);
            size_t off = (size_t)col * NKV + rowBase + ty * 8;
            *(uint4*)&g_vth[off] = *(uint4*)hb;
            *(uint4*)&g_vtl[off] = *(uint4*)lb;
        }
    } else {
        __nv_bfloat16* dh = z ? g_kh : g_qh;
        __nv_bfloat16* dl = z ? g_kl : g_ql;
#pragma unroll
        for (int i = 0; i < 8; ++i) {
            int row = rowBase + ty * 8 + i;
            __align__(16) __nv_bfloat16 hb[8], lb[8];
#pragma unroll
            for (int e = 0; e < 8; ++e) {
                int col = colBase + tx * 8 + e;
                split_bf16((acc[i][e] + b[col]) * scale, hb[e], lb[e]);
            }
            size_t off = (size_t)row * DDIM + colBase + tx * 8;
            *(uint4*)&dh[off] = *(uint4*)hb;
            *(uint4*)&dl[off] = *(uint4*)lb;
        }
    }
}

// ---------------------------------------------------------------------------
// HMMA GEMM: D[128,128] = A[128,K]*B[128,K]^T with split-bf16 (3 products).
// 256 thr, 8 warps (4 m x 2 n), warp tile 32x64, BK=64, double-buffered
// cp.async. SMEM rows padded to 72 bf16 (144B) => conflict-free ldmatrix.
// EXP_MODE=1: A=q,B=k, epi: P=exp(D) split-store + row-sum partials.
// EXP_MODE=0: A=P,B=V^T, epi: out = D * linv[row].
// ---------------------------------------------------------------------------
#define ARR_B   18432            // 128 * 144
#define STAGE_B (4 * ARR_B)      // Ah | Al | Bh | Bl
#define SMEM_B  (2 * STAGE_B)    // 147456

template <bool EXP_MODE>
__global__ __launch_bounds__(256, 1) void gemm_kernel(float* __restrict__ outp)
{
    constexpr int LD = EXP_MODE ? DDIM : NKV;   // k-stride of A and B
    constexpr int NC = EXP_MODE ? (DDIM / 64) : (NKV / 64);

    const __nv_bfloat16* __restrict__ Ah = EXP_MODE ? g_qh : g_ph;
    const __nv_bfloat16* __restrict__ Al = EXP_MODE ? g_ql : g_pl;
    const __nv_bfloat16* __restrict__ Bh = EXP_MODE ? g_kh : g_vth;
    const __nv_bfloat16* __restrict__ Bl = EXP_MODE ? g_kl : g_vtl;

    extern __shared__ char smc[];
    const uint32_t smb = smem_u32(smc);

    const int tid = threadIdx.x;
    const int lane = tid & 31, w = tid >> 5;
    const int wm = w & 3, wn = w >> 2;
    const int rowBase = blockIdx.y * 128;
    const int nBase = blockIdx.x * 128;

    float acc[2][8][4];
#pragma unroll
    for (int i = 0; i < 2; ++i)
#pragma unroll
        for (int j = 0; j < 8; ++j)
#pragma unroll
            for (int e = 0; e < 4; ++e) acc[i][j][e] = 0.0f;

    // cp.async stage loader: thread handles 4 chunks of 16B per array
    auto load_stage = [&](int buf, int kc) {
        const int kBase = kc * 64;
        const uint32_t sb = smb + buf * STAGE_B;
#pragma unroll
        for (int it = 0; it < 4; ++it) {
            int idx = tid + it * 256;
            int r = idx >> 3, cc = idx & 7;
            uint32_t so = (uint32_t)(r * 144 + cc * 16);
            size_t goA = (size_t)(rowBase + r) * LD + kBase + cc * 8;
            size_t goB = (size_t)(nBase + r) * LD + kBase + cc * 8;
            CP16(sb + so,             Ah + goA);
            CP16(sb + ARR_B + so,     Al + goA);
            CP16(sb + 2 * ARR_B + so, Bh + goB);
            CP16(sb + 3 * ARR_B + so, Bl + goB);
        }
    };

    // ldmatrix address components
    const uint32_t aOff = (uint32_t)((wm * 32 + (lane & 15)) * 144 + ((lane >> 4) * 8) * 2);
    const int g = lane >> 3;
    const uint32_t bOff = (uint32_t)((wn * 64 + ((g >> 1) << 3) + (lane & 7)) * 144
                                     + ((g & 1) << 3) * 2);

    auto compute = [&](int buf) {
        const uint32_t sb = smb + buf * STAGE_B;
        const uint32_t aH = sb + aOff, aL = sb + ARR_B + aOff;
        const uint32_t bH = sb + 2 * ARR_B + bOff, bL = sb + 3 * ARR_B + bOff;
#pragma unroll
        for (int kk = 0; kk < 4; ++kk) {
            uint32_t ah[2][4], al[2][4], bh[4][4], bl[4][4];
#pragma unroll
            for (int i = 0; i < 2; ++i) {
                LDSM_X4(ah[i][0], ah[i][1], ah[i][2], ah[i][3], aH + i * 2304 + kk * 32);
                LDSM_X4(al[i][0], al[i][1], al[i][2], al[i][3], aL + i * 2304 + kk * 32);
            }
#pragma unroll
            for (int j = 0; j < 4; ++j) {
                LDSM_X4(bh[j][0], bh[j][1], bh[j][2], bh[j][3], bH + j * 2304 + kk * 32);
                LDSM_X4(bl[j][0], bl[j][1], bl[j][2], bl[j][3], bL + j * 2304 + kk * 32);
            }
#pragma unroll
            for (int i = 0; i < 2; ++i)
#pragma unroll
                for (int jj = 0; jj < 8; ++jj) {
                    MMA16816(acc[i][jj], ah[i], &bh[jj >> 1][(jj & 1) * 2]);
                    MMA16816(acc[i][jj], ah[i], &bl[jj >> 1][(jj & 1) * 2]);
                    MMA16816(acc[i][jj], al[i], &bh[jj >> 1][(jj & 1) * 2]);
                }
        }
    };

    load_stage(0, 0);
    CP_COMMIT;
#pragma unroll 1
    for (int c = 0; c < NC; ++c) {
        if (c + 1 < NC) {
            load_stage((c + 1) & 1, c + 1);
            CP_COMMIT;
            CP_WAIT1;
        } else {
            CP_WAIT0;
        }
        __syncthreads();
        compute(c & 1);
        __syncthreads();
    }

    // ---- epilogue ----
    // thread owns: rows rowBase + wm*32 + i*16 + (lane>>2) (+8),
    //              cols nBase + wn*64 + jj*8 + (lane&3)*2 (+1)
    if (EXP_MODE) {
        float ls[2][2] = {{0.0f, 0.0f}, {0.0f, 0.0f}};
#pragma unroll
        for (int i = 0; i < 2; ++i) {
            const int row0 = rowBase + wm * 32 + i * 16 + (lane >> 2);
#pragma unroll
            for (int jj = 0; jj < 8; ++jj) {
                const int col = nBase + wn * 64 + jj * 8 + (lane & 3) * 2;
                float p0 = __expf(acc[i][jj][0]);
                float p1 = __expf(acc[i][jj][1]);
                float p2 = __expf(acc[i][jj][2]);
                float p3 = __expf(acc[i][jj][3]);
                ls[i][0] += p0 + p1;
                ls[i][1] += p2 + p3;
                __nv_bfloat16 h0, l0, h1, l1;
                split_bf16(p0, h0, l0); split_bf16(p1, h1, l1);
                *(__nv_bfloat162*)&g_ph[(size_t)row0 * NKV + col] =
                    __nv_bfloat162(h0, h1);
                *(__nv_bfloat162*)&g_pl[(size_t)row0 * NKV + col] =
                    __nv_bfloat162(l0, l1);
                split_bf16(p2, h0, l0); split_bf16(p3, h1, l1);
                *(__nv_bfloat162*)&g_ph[(size_t)(row0 + 8) * NKV + col] =
                    __nv_bfloat162(h0, h1);
                *(__nv_bfloat162*)&g_pl[(size_t)(row0 + 8) * NKV + col] =
                    __nv_bfloat162(l0, l1);
            }
        }
        // quad-reduce across the 4 lanes sharing a row (lane&3 = n position)
        const int slot = blockIdx.x * 2 + wn;
#pragma unroll
        for (int i = 0; i < 2; ++i)
#pragma unroll
            for (int pr = 0; pr < 2; ++pr) {
                float s = ls[i][pr];
                s += __shfl_xor_sync(0xffffffffu, s, 1);
                s += __shfl_xor_sync(0xffffffffu, s, 2);
                if ((lane & 3) == 0) {
                    int row = rowBase + wm * 32 + i * 16 + (lane >> 2) + pr * 8;
                    g_lpart[(size_t)slot * NQ + row] = s;
                }
            }
    } else {
#pragma unroll
        for (int i = 0; i < 2; ++i) {
            const int row0 = rowBase + wm * 32 + i * 16 + (lane >> 2);
            const float inv0 = g_linv[row0];
            const float inv1 = g_linv[row0 + 8];
#pragma unroll
            for (int jj = 0; jj < 8; ++jj) {
                const int col = nBase + wn * 64 + jj * 8 + (lane & 3) * 2;
                float2 r0, r1;
                r0.x = acc[i][jj][0] * inv0; r0.y = acc[i][jj][1] * inv0;
                r1.x = acc[i][jj][2] * inv1; r1.y = acc[i][jj][3] * inv1;
                *(float2*)&outp[(size_t)row0 * DDIM + col] = r0;
                *(float2*)&outp[(size_t)(row0 + 8) * DDIM + col] = r1;
            }
        }
    }
}

// ---------------------------------------------------------------------------
__global__ void lred_kernel()
{
    int row = blockIdx.x * 256 + threadIdx.x;
    float s = 0.0f;
#pragma unroll 8
    for (int j = 0; j < 128; ++j) s += g_lpart[(size_t)j * NQ + row];
    g_linv[row] = 1.0f / s;
}

// ---------------------------------------------------------------------------
extern "C" void kernel_launch(void* const* d_in, const int* in_sizes, int n_in,
                              void* d_out, int out_size)
{
    const float* x   = (const float*)d_in[0];
    const float* dom = (const float*)d_in[1];
    const float* Wq  = (const float*)d_in[2];
    const float* bq  = (const float*)d_in[3];
    const float* Wk  = (const float*)d_in[4];
    const float* bk  = (const float*)d_in[5];
    const float* Wv  = (const float*)d_in[6];
    const float* bv  = (const float*)d_in[7];
    float* out = (float*)d_out;

    cudaFuncSetAttribute(gemm_kernel<true>,
                         cudaFuncAttributeMaxDynamicSharedMemorySize, SMEM_B);
    cudaFuncSetAttribute(gemm_kernel<false>,
                         cudaFuncAttributeMaxDynamicSharedMemorySize, SMEM_B);

    dim3 gproj(DDIM / 128, NQ / 128, 3);
    proj_kernel<<<gproj, 256>>>(x, dom, Wq, bq, Wk, bk, Wv, bv);

    // P = exp(q k^T)
    gemm_kernel<true><<<dim3(NKV / 128, NQ / 128), 256, SMEM_B>>>(nullptr);

    lred_kernel<<<NQ / 256, 256>>>();

    // O = (P V) * linv
    gemm_kernel<false><<<dim3(DDIM / 128, NQ / 128), 256, SMEM_B>>>(out);
}

// round 9
// speedup vs baseline: 3.6666x; 1.1618x over previous
#include <cuda_runtime.h>
#include <cuda_bf16.h>
#include <cuda_fp16.h>
#include <cstdint>

#define NQ 8192
#define NKV 8192
#define DDIM 512
static constexpr float QSCALE = 0.044194173824159216f; // 1/sqrt(512)

// ---------------- scratch (device globals; no allocation) ----------------
__device__ __align__(256) __nv_bfloat16 g_qh[NQ * DDIM];
__device__ __align__(256) __nv_bfloat16 g_ql[NQ * DDIM];
__device__ __align__(256) __nv_bfloat16 g_kh[NKV * DDIM];
__device__ __align__(256) __nv_bfloat16 g_kl[NKV * DDIM];
__device__ __align__(256) __half g_vth[DDIM * NKV];   // V^T hi (fp16) [512, 8192]
__device__ __align__(256) __half g_vtl[DDIM * NKV];   // V^T lo (fp16)
__device__ __align__(256) __half g_p[(size_t)NQ * NKV];  // P = exp(scores), fp16
__device__ float g_lpart[128 * NQ];   // [slot][row]
__device__ float g_linv[NQ];

// ---------------- helpers ----------------
__device__ __forceinline__ uint32_t smem_u32(const void* p) {
    uint32_t a;
    asm("{ .reg .u64 t; cvta.to.shared.u64 t, %1; cvt.u32.u64 %0, t; }"
        : "=r"(a) : "l"(p));
    return a;
}

#define CP16(sa, gp) \
    asm volatile("cp.async.cg.shared.global [%0], [%1], 16;" \
                 :: "r"(sa), "l"(gp) : "memory")
#define CP_COMMIT asm volatile("cp.async.commit_group;" ::: "memory")
#define CP_WAITG(n) asm volatile("cp.async.wait_group %0;" :: "n"(n) : "memory")

#define LDSM_X4(r0, r1, r2, r3, addr) \
    asm volatile("ldmatrix.sync.aligned.m8n8.x4.shared.b16 {%0,%1,%2,%3}, [%4];" \
                 : "=r"(r0), "=r"(r1), "=r"(r2), "=r"(r3) : "r"(addr))

#define MMA_BF16(d, a, b) \
    asm volatile("mma.sync.aligned.m16n8k16.row.col.f32.bf16.bf16.f32 " \
                 "{%0,%1,%2,%3}, {%4,%5,%6,%7}, {%8,%9}, {%0,%1,%2,%3};" \
                 : "+f"((d)[0]), "+f"((d)[1]), "+f"((d)[2]), "+f"((d)[3]) \
                 : "r"((a)[0]), "r"((a)[1]), "r"((a)[2]), "r"((a)[3]), \
                   "r"((b)[0]), "r"((b)[1]))

#define MMA_F16(d, a, b) \
    asm volatile("mma.sync.aligned.m16n8k16.row.col.f32.f16.f16.f32 " \
                 "{%0,%1,%2,%3}, {%4,%5,%6,%7}, {%8,%9}, {%0,%1,%2,%3};" \
                 : "+f"((d)[0]), "+f"((d)[1]), "+f"((d)[2]), "+f"((d)[3]) \
                 : "r"((a)[0]), "r"((a)[1]), "r"((a)[2]), "r"((a)[3]), \
                   "r"((b)[0]), "r"((b)[1]))

__device__ __forceinline__ void split_bf16(float x, __nv_bfloat16& h, __nv_bfloat16& l) {
    h = __float2bfloat16(x);
    l = __float2bfloat16(x - __bfloat162float(h));
}
__device__ __forceinline__ void split_h16(float x, __half& h, __half& l) {
    h = __float2half_rn(x);
    l = __float2half_rn(x - __half2float(h));
}

// ---------------------------------------------------------------------------
// Projection (fp32 FFMA, 128x128 tile) -> split-bf16 q, k; split-fp16 V^T.
// ---------------------------------------------------------------------------
__global__ __launch_bounds__(256) void proj_kernel(
    const float* __restrict__ x, const float* __restrict__ dom,
    const float* __restrict__ Wq, const float* __restrict__ bq,
    const float* __restrict__ Wk, const float* __restrict__ bk,
    const float* __restrict__ Wv, const float* __restrict__ bv)
{
    __shared__ float As[16][132];
    __shared__ float Bs[16][132];

    const int z = blockIdx.z;
    const float* A = (z == 0) ? x : dom;
    const float* W = (z == 0) ? Wq : (z == 1 ? Wk : Wv);
    const float* b = (z == 0) ? bq : (z == 1 ? bk : bv);
    const float scale = (z == 0) ? QSCALE : 1.0f;

    const int tid = threadIdx.x;
    const int tx = tid & 15, ty = tid >> 4;
    const int rowBase = blockIdx.y * 128;
    const int colBase = blockIdx.x * 128;

    float acc[8][8];
#pragma unroll
    for (int i = 0; i < 8; ++i)
#pragma unroll
        for (int j = 0; j < 8; ++j) acc[i][j] = 0.0f;

    for (int kt = 0; kt < DDIM / 16; ++kt) {
        const int k0 = kt * 16;
#pragma unroll
        for (int it = 0; it < 2; ++it) {
            int idx = tid + 256 * it;
            int r = idx >> 2, c4 = idx & 3;
            float4 a = *(const float4*)&A[(size_t)(rowBase + r) * DDIM + k0 + c4 * 4];
            As[c4 * 4 + 0][r] = a.x; As[c4 * 4 + 1][r] = a.y;
            As[c4 * 4 + 2][r] = a.z; As[c4 * 4 + 3][r] = a.w;
            float4 w = *(const float4*)&W[(size_t)(colBase + r) * DDIM + k0 + c4 * 4];
            Bs[c4 * 4 + 0][r] = w.x; Bs[c4 * 4 + 1][r] = w.y;
            Bs[c4 * 4 + 2][r] = w.z; Bs[c4 * 4 + 3][r] = w.w;
        }
        __syncthreads();
#pragma unroll
        for (int k = 0; k < 16; ++k) {
            float ar[8], br[8];
            *(float4*)&ar[0] = *(const float4*)&As[k][ty * 8];
            *(float4*)&ar[4] = *(const float4*)&As[k][ty * 8 + 4];
            *(float4*)&br[0] = *(const float4*)&Bs[k][tx * 8];
            *(float4*)&br[4] = *(const float4*)&Bs[k][tx * 8 + 4];
#pragma unroll
            for (int i = 0; i < 8; ++i)
#pragma unroll
                for (int j = 0; j < 8; ++j) acc[i][j] += ar[i] * br[j];
        }
        __syncthreads();
    }

    if (z == 2) {
        // V^T split-fp16: vt[col][row], rows contiguous
#pragma unroll
        for (int j = 0; j < 8; ++j) {
            int col = colBase + tx * 8 + j;
            float bias = b[col];
            __align__(16) __half hb[8], lb[8];
#pragma unroll
            for (int i = 0; i < 8; ++i) split_h16(acc[i][j] + bias, hb[i], lb[i]);
            size_t off = (size_t)col * NKV + rowBase + ty * 8;
            *(uint4*)&g_vth[off] = *(uint4*)hb;
            *(uint4*)&g_vtl[off] = *(uint4*)lb;
        }
    } else {
        __nv_bfloat16* dh = z ? g_kh : g_qh;
        __nv_bfloat16* dl = z ? g_kl : g_ql;
#pragma unroll
        for (int i = 0; i < 8; ++i) {
            int row = rowBase + ty * 8 + i;
            __align__(16) __nv_bfloat16 hb[8], lb[8];
#pragma unroll
            for (int e = 0; e < 8; ++e) {
                int col = colBase + tx * 8 + e;
                split_bf16((acc[i][e] + b[col]) * scale, hb[e], lb[e]);
            }
            size_t off = (size_t)row * DDIM + colBase + tx * 8;
            *(uint4*)&dh[off] = *(uint4*)hb;
            *(uint4*)&dl[off] = *(uint4*)lb;
        }
    }
}

// ---------------------------------------------------------------------------
// Shared GEMM geometry: 128x128 block tile, 8 warps (4m x 2n), warp 32x64,
// BK=64, SMEM rows padded to 144B, 3-stage cp.async pipeline, 1 sync/chunk.
// ---------------------------------------------------------------------------
#define ARR_B    18432           // 128 rows * 144 B
#define STAGE1_B (4 * ARR_B)     // GEMM1: qh | ql | kh | kl
#define SMEM1_B  (3 * STAGE1_B)  // 221184
#define STAGE2_B (3 * ARR_B)     // GEMM2: P | Vh | Vl
#define SMEM2_B  (3 * STAGE2_B)  // 165888

// ---- GEMM1: P = exp(q k^T), split-bf16 3-product, K=512 ----
__global__ __launch_bounds__(256, 1) void gemm1_kernel()
{
    constexpr int NC = DDIM / 64;   // 8
    extern __shared__ char smc[];
    const uint32_t smb = smem_u32(smc);

    const int tid = threadIdx.x;
    const int lane = tid & 31, w = tid >> 5;
    const int wm = w & 3, wn = w >> 2;
    const int rowBase = blockIdx.y * 128;
    const int nBase = blockIdx.x * 128;

    float acc[2][8][4];
#pragma unroll
    for (int i = 0; i < 2; ++i)
#pragma unroll
        for (int j = 0; j < 8; ++j)
#pragma unroll
            for (int e = 0; e < 4; ++e) acc[i][j][e] = 0.0f;

    auto load_stage = [&](int buf, int kc) {
        const int kBase = kc * 64;
        const uint32_t sb = smb + buf * STAGE1_B;
#pragma unroll
        for (int it = 0; it < 4; ++it) {
            int idx = tid + it * 256;
            int r = idx >> 3, cc = idx & 7;
            uint32_t so = (uint32_t)(r * 144 + cc * 16);
            size_t goA = (size_t)(rowBase + r) * DDIM + kBase + cc * 8;
            size_t goB = (size_t)(nBase + r) * DDIM + kBase + cc * 8;
            CP16(sb + so,             g_qh + goA);
            CP16(sb + ARR_B + so,     g_ql + goA);
            CP16(sb + 2 * ARR_B + so, g_kh + goB);
            CP16(sb + 3 * ARR_B + so, g_kl + goB);
        }
        CP_COMMIT;
    };

    const uint32_t aOff = (uint32_t)((wm * 32 + (lane & 15)) * 144 + ((lane >> 4) * 8) * 2);
    const int g = lane >> 3;
    const uint32_t bOff = (uint32_t)((wn * 64 + ((g >> 1) << 3) + (lane & 7)) * 144
                                     + ((g & 1) << 3) * 2);

    load_stage(0, 0);
    load_stage(1, 1);

#pragma unroll 1
    for (int c = 0; c < NC; ++c) {
        if (c == NC - 1) { CP_WAITG(0); } else { CP_WAITG(1); }
        __syncthreads();
        if (c + 2 < NC) load_stage((c + 2) % 3, c + 2);

        const uint32_t sb = smb + (c % 3) * STAGE1_B;
        const uint32_t aH = sb + aOff, aL = sb + ARR_B + aOff;
        const uint32_t bH = sb + 2 * ARR_B + bOff, bL = sb + 3 * ARR_B + bOff;
#pragma unroll
        for (int kk = 0; kk < 4; ++kk) {
            uint32_t ah[2][4], al[2][4], bh[4][4], bl[4][4];
#pragma unroll
            for (int i = 0; i < 2; ++i) {
                LDSM_X4(ah[i][0], ah[i][1], ah[i][2], ah[i][3], aH + i * 2304 + kk * 32);
                LDSM_X4(al[i][0], al[i][1], al[i][2], al[i][3], aL + i * 2304 + kk * 32);
            }
#pragma unroll
            for (int j = 0; j < 4; ++j) {
                LDSM_X4(bh[j][0], bh[j][1], bh[j][2], bh[j][3], bH + j * 2304 + kk * 32);
                LDSM_X4(bl[j][0], bl[j][1], bl[j][2], bl[j][3], bL + j * 2304 + kk * 32);
            }
#pragma unroll
            for (int i = 0; i < 2; ++i)
#pragma unroll
                for (int jj = 0; jj < 8; ++jj) {
                    MMA_BF16(acc[i][jj], ah[i], &bh[jj >> 1][(jj & 1) * 2]);
                    MMA_BF16(acc[i][jj], ah[i], &bl[jj >> 1][(jj & 1) * 2]);
                    MMA_BF16(acc[i][jj], al[i], &bh[jj >> 1][(jj & 1) * 2]);
                }
        }
    }

    // ---- epilogue: P = exp(acc) -> fp16, plus deterministic row-sum partials
    float ls[2][2] = {{0.0f, 0.0f}, {0.0f, 0.0f}};
#pragma unroll
    for (int i = 0; i < 2; ++i) {
        const int row0 = rowBase + wm * 32 + i * 16 + (lane >> 2);
#pragma unroll
        for (int jj = 0; jj < 8; ++jj) {
            const int col = nBase + wn * 64 + jj * 8 + (lane & 3) * 2;
            float p0 = __expf(acc[i][jj][0]);
            float p1 = __expf(acc[i][jj][1]);
            float p2 = __expf(acc[i][jj][2]);
            float p3 = __expf(acc[i][jj][3]);
            ls[i][0] += p0 + p1;
            ls[i][1] += p2 + p3;
            *(__half2*)&g_p[(size_t)row0 * NKV + col] = __floats2half2_rn(p0, p1);
            *(__half2*)&g_p[(size_t)(row0 + 8) * NKV + col] = __floats2half2_rn(p2, p3);
        }
    }
    const int slot = blockIdx.x * 2 + wn;
#pragma unroll
    for (int i = 0; i < 2; ++i)
#pragma unroll
        for (int pr = 0; pr < 2; ++pr) {
            float s = ls[i][pr];
            s += __shfl_xor_sync(0xffffffffu, s, 1);
            s += __shfl_xor_sync(0xffffffffu, s, 2);
            if ((lane & 3) == 0) {
                int row = rowBase + wm * 32 + i * 16 + (lane >> 2) + pr * 8;
                g_lpart[(size_t)slot * NQ + row] = s;
            }
        }
}

// ---- GEMM2: O = (P V) * linv, fp16 2-product, K=8192 ----
__global__ __launch_bounds__(256, 1) void gemm2_kernel(float* __restrict__ outp)
{
    constexpr int NC = NKV / 64;    // 128
    extern __shared__ char smc[];
    const uint32_t smb = smem_u32(smc);

    const int tid = threadIdx.x;
    const int lane = tid & 31, w = tid >> 5;
    const int wm = w & 3, wn = w >> 2;
    const int rowBase = blockIdx.y * 128;
    const int nBase = blockIdx.x * 128;

    float acc[2][8][4];
#pragma unroll
    for (int i = 0; i < 2; ++i)
#pragma unroll
        for (int j = 0; j < 8; ++j)
#pragma unroll
            for (int e = 0; e < 4; ++e) acc[i][j][e] = 0.0f;

    auto load_stage = [&](int buf, int kc) {
        const int kBase = kc * 64;
        const uint32_t sb = smb + buf * STAGE2_B;
#pragma unroll
        for (int it = 0; it < 4; ++it) {
            int idx = tid + it * 256;
            int r = idx >> 3, cc = idx & 7;
            uint32_t so = (uint32_t)(r * 144 + cc * 16);
            size_t goA = (size_t)(rowBase + r) * NKV + kBase + cc * 8;
            size_t goB = (size_t)(nBase + r) * NKV + kBase + cc * 8;
            CP16(sb + so,             g_p + goA);
            CP16(sb + ARR_B + so,     g_vth + goB);
            CP16(sb + 2 * ARR_B + so, g_vtl + goB);
        }
        CP_COMMIT;
    };

    const uint32_t aOff = (uint32_t)((wm * 32 + (lane & 15)) * 144 + ((lane >> 4) * 8) * 2);
    const int g = lane >> 3;
    const uint32_t bOff = (uint32_t)((wn * 64 + ((g >> 1) << 3) + (lane & 7)) * 144
                                     + ((g & 1) << 3) * 2);

    load_stage(0, 0);
    load_stage(1, 1);

#pragma unroll 1
    for (int c = 0; c < NC; ++c) {
        if (c == NC - 1) { CP_WAITG(0); } else { CP_WAITG(1); }
        __syncthreads();
        if (c + 2 < NC) load_stage((c + 2) % 3, c + 2);

        const uint32_t sb = smb + (c % 3) * STAGE2_B;
        const uint32_t aP = sb + aOff;
        const uint32_t bH = sb + ARR_B + bOff, bL = sb + 2 * ARR_B + bOff;
#pragma unroll
        for (int kk = 0; kk < 4; ++kk) {
            uint32_t ap[2][4], vh[4][4], vl[4][4];
#pragma unroll
            for (int i = 0; i < 2; ++i)
                LDSM_X4(ap[i][0], ap[i][1], ap[i][2], ap[i][3], aP + i * 2304 + kk * 32);
#pragma unroll
            for (int j = 0; j < 4; ++j) {
                LDSM_X4(vh[j][0], vh[j][1], vh[j][2], vh[j][3], bH + j * 2304 + kk * 32);
                LDSM_X4(vl[j][0], vl[j][1], vl[j][2], vl[j][3], bL + j * 2304 + kk * 32);
            }
#pragma unroll
            for (int i = 0; i < 2; ++i)
#pragma unroll
                for (int jj = 0; jj < 8; ++jj) {
                    MMA_F16(acc[i][jj], ap[i], &vh[jj >> 1][(jj & 1) * 2]);
                    MMA_F16(acc[i][jj], ap[i], &vl[jj >> 1][(jj & 1) * 2]);
                }
        }
    }

    // ---- epilogue: out = acc * linv[row]
#pragma unroll
    for (int i = 0; i < 2; ++i) {
        const int row0 = rowBase + wm * 32 + i * 16 + (lane >> 2);
        const float inv0 = g_linv[row0];
        const float inv1 = g_linv[row0 + 8];
#pragma unroll
        for (int jj = 0; jj < 8; ++jj) {
            const int col = nBase + wn * 64 + jj * 8 + (lane & 3) * 2;
            float2 r0, r1;
            r0.x = acc[i][jj][0] * inv0; r0.y = acc[i][jj][1] * inv0;
            r1.x = acc[i][jj][2] * inv1; r1.y = acc[i][jj][3] * inv1;
            *(float2*)&outp[(size_t)row0 * DDIM + col] = r0;
            *(float2*)&outp[(size_t)(row0 + 8) * DDIM + col] = r1;
        }
    }
}

// ---------------------------------------------------------------------------
__global__ void lred_kernel()
{
    int row = blockIdx.x * 256 + threadIdx.x;
    float s = 0.0f;
#pragma unroll 8
    for (int j = 0; j < 128; ++j) s += g_lpart[(size_t)j * NQ + row];
    g_linv[row] = 1.0f / s;
}

// ---------------------------------------------------------------------------
extern "C" void kernel_launch(void* const* d_in, const int* in_sizes, int n_in,
                              void* d_out, int out_size)
{
    const float* x   = (const float*)d_in[0];
    const float* dom = (const float*)d_in[1];
    const float* Wq  = (const float*)d_in[2];
    const float* bq  = (const float*)d_in[3];
    const float* Wk  = (const float*)d_in[4];
    const float* bk  = (const float*)d_in[5];
    const float* Wv  = (const float*)d_in[6];
    const float* bv  = (const float*)d_in[7];
    float* out = (float*)d_out;

    cudaFuncSetAttribute(gemm1_kernel,
                         cudaFuncAttributeMaxDynamicSharedMemorySize, SMEM1_B);
    cudaFuncSetAttribute(gemm2_kernel,
                         cudaFuncAttributeMaxDynamicSharedMemorySize, SMEM2_B);

    dim3 gproj(DDIM / 128, NQ / 128, 3);
    proj_kernel<<<gproj, 256>>>(x, dom, Wq, bq, Wk, bk, Wv, bv);

    // P = exp(q k^T)
    gemm1_kernel<<<dim3(NKV / 128, NQ / 128), 256, SMEM1_B>>>();

    lred_kernel<<<NQ / 256, 256>>>();

    // O = (P V) * linv
    gemm2_kernel<<<dim3(DDIM / 128, NQ / 128), 256, SMEM2_B>>>(out);
}

// round 10
// speedup vs baseline: 4.4059x; 1.2016x over previous
#include <cuda_runtime.h>
#include <cuda_bf16.h>
#include <cuda_fp16.h>
#include <cstdint>

#define NQ 8192
#define NKV 8192
#define DDIM 512
static constexpr float QSCALE = 0.044194173824159216f; // 1/sqrt(512)

// ---------------- scratch (device globals; no allocation) ----------------
__device__ __align__(256) __half g_q[NQ * DDIM];      // q, single fp16 (scaled)
__device__ __align__(256) __half g_kh[NKV * DDIM];    // k hi (fp16)
__device__ __align__(256) __half g_kl[NKV * DDIM];    // k lo (fp16)
__device__ __align__(256) __half g_vth[DDIM * NKV];   // V^T hi (fp16) [512, 8192]
__device__ __align__(256) __half g_vtl[DDIM * NKV];   // V^T lo (fp16)
__device__ __align__(256) __half g_p[(size_t)NQ * NKV];  // P = exp(scores), fp16
__device__ float g_lpart[128 * NQ];   // [slot][row]
__device__ float g_linv[NQ];

// ---------------- helpers ----------------
__device__ __forceinline__ uint32_t smem_u32(const void* p) {
    uint32_t a;
    asm("{ .reg .u64 t; cvta.to.shared.u64 t, %1; cvt.u32.u64 %0, t; }"
        : "=r"(a) : "l"(p));
    return a;
}

#define CP16(sa, gp) \
    asm volatile("cp.async.cg.shared.global [%0], [%1], 16;" \
                 :: "r"(sa), "l"(gp) : "memory")
#define CP_COMMIT asm volatile("cp.async.commit_group;" ::: "memory")
#define CP_WAITG(n) asm volatile("cp.async.wait_group %0;" :: "n"(n) : "memory")

#define LDSM_X4(r0, r1, r2, r3, addr) \
    asm volatile("ldmatrix.sync.aligned.m8n8.x4.shared.b16 {%0,%1,%2,%3}, [%4];" \
                 : "=r"(r0), "=r"(r1), "=r"(r2), "=r"(r3) : "r"(addr))

#define MMA_F16(d, a, b) \
    asm volatile("mma.sync.aligned.m16n8k16.row.col.f32.f16.f16.f32 " \
                 "{%0,%1,%2,%3}, {%4,%5,%6,%7}, {%8,%9}, {%0,%1,%2,%3};" \
                 : "+f"((d)[0]), "+f"((d)[1]), "+f"((d)[2]), "+f"((d)[3]) \
                 : "r"((a)[0]), "r"((a)[1]), "r"((a)[2]), "r"((a)[3]), \
                   "r"((b)[0]), "r"((b)[1]))

__device__ __forceinline__ void split_h16(float x, __half& h, __half& l) {
    h = __float2half_rn(x);
    l = __float2half_rn(x - __half2float(h));
}

// ---------------------------------------------------------------------------
// Projection (fp32 FFMA, 128x128 tile) -> fp16 q; split-fp16 k and V^T.
// ---------------------------------------------------------------------------
__global__ __launch_bounds__(256) void proj_kernel(
    const float* __restrict__ x, const float* __restrict__ dom,
    const float* __restrict__ Wq, const float* __restrict__ bq,
    const float* __restrict__ Wk, const float* __restrict__ bk,
    const float* __restrict__ Wv, const float* __restrict__ bv)
{
    __shared__ float As[16][132];
    __shared__ float Bs[16][132];

    const int z = blockIdx.z;
    const float* A = (z == 0) ? x : dom;
    const float* W = (z == 0) ? Wq : (z == 1 ? Wk : Wv);
    const float* b = (z == 0) ? bq : (z == 1 ? bk : bv);
    const float scale = (z == 0) ? QSCALE : 1.0f;

    const int tid = threadIdx.x;
    const int tx = tid & 15, ty = tid >> 4;
    const int rowBase = blockIdx.y * 128;
    const int colBase = blockIdx.x * 128;

    float acc[8][8];
#pragma unroll
    for (int i = 0; i < 8; ++i)
#pragma unroll
        for (int j = 0; j < 8; ++j) acc[i][j] = 0.0f;

    for (int kt = 0; kt < DDIM / 16; ++kt) {
        const int k0 = kt * 16;
#pragma unroll
        for (int it = 0; it < 2; ++it) {
            int idx = tid + 256 * it;
            int r = idx >> 2, c4 = idx & 3;
            float4 a = *(const float4*)&A[(size_t)(rowBase + r) * DDIM + k0 + c4 * 4];
            As[c4 * 4 + 0][r] = a.x; As[c4 * 4 + 1][r] = a.y;
            As[c4 * 4 + 2][r] = a.z; As[c4 * 4 + 3][r] = a.w;
            float4 w = *(const float4*)&W[(size_t)(colBase + r) * DDIM + k0 + c4 * 4];
            Bs[c4 * 4 + 0][r] = w.x; Bs[c4 * 4 + 1][r] = w.y;
            Bs[c4 * 4 + 2][r] = w.z; Bs[c4 * 4 + 3][r] = w.w;
        }
        __syncthreads();
#pragma unroll
        for (int k = 0; k < 16; ++k) {
            float ar[8], br[8];
            *(float4*)&ar[0] = *(const float4*)&As[k][ty * 8];
            *(float4*)&ar[4] = *(const float4*)&As[k][ty * 8 + 4];
            *(float4*)&br[0] = *(const float4*)&Bs[k][tx * 8];
            *(float4*)&br[4] = *(const float4*)&Bs[k][tx * 8 + 4];
#pragma unroll
            for (int i = 0; i < 8; ++i)
#pragma unroll
                for (int j = 0; j < 8; ++j) acc[i][j] += ar[i] * br[j];
        }
        __syncthreads();
    }

    if (z == 2) {
        // V^T split-fp16: vt[col][row], rows contiguous
#pragma unroll
        for (int j = 0; j < 8; ++j) {
            int col = colBase + tx * 8 + j;
            float bias = b[col];
            __align__(16) __half hb[8], lb[8];
#pragma unroll
            for (int i = 0; i < 8; ++i) split_h16(acc[i][j] + bias, hb[i], lb[i]);
            size_t off = (size_t)col * NKV + rowBase + ty * 8;
            *(uint4*)&g_vth[off] = *(uint4*)hb;
            *(uint4*)&g_vtl[off] = *(uint4*)lb;
        }
    } else if (z == 1) {
        // k split-fp16
#pragma unroll
        for (int i = 0; i < 8; ++i) {
            int row = rowBase + ty * 8 + i;
            __align__(16) __half hb[8], lb[8];
#pragma unroll
            for (int e = 0; e < 8; ++e) {
                int col = colBase + tx * 8 + e;
                split_h16(acc[i][e] + b[col], hb[e], lb[e]);
            }
            size_t off = (size_t)row * DDIM + colBase + tx * 8;
            *(uint4*)&g_kh[off] = *(uint4*)hb;
            *(uint4*)&g_kl[off] = *(uint4*)lb;
        }
    } else {
        // q single fp16, scaled
#pragma unroll
        for (int i = 0; i < 8; ++i) {
            int row = rowBase + ty * 8 + i;
            __align__(16) __half hb[8];
#pragma unroll
            for (int e = 0; e < 8; ++e) {
                int col = colBase + tx * 8 + e;
                hb[e] = __float2half_rn((acc[i][e] + b[col]) * scale);
            }
            size_t off = (size_t)row * DDIM + colBase + tx * 8;
            *(uint4*)&g_q[off] = *(uint4*)hb;
        }
    }
}

// ---------------------------------------------------------------------------
// GEMM geometry: 128x128 block tile, 8 warps (4m x 2n), warp 32x64, BK=64,
// SMEM rows padded to 144B, 2-stage cp.async pipeline, 2 CTAs/SM.
// Both GEMMs: 2 fp16 MMA products (A single, B hi/lo).
// ---------------------------------------------------------------------------
#define ARR_B    18432           // 128 rows * 144 B
#define STAGE_B  (3 * ARR_B)     // A | Bh | Bl
#define SMEM_GB  (2 * STAGE_B)   // 110592

// ---- GEMM1: P = exp(q k^T), K=512 ----
__global__ __launch_bounds__(256, 2) void gemm1_kernel()
{
    constexpr int NC = DDIM / 64;   // 8
    extern __shared__ char smc[];
    const uint32_t smb = smem_u32(smc);

    const int tid = threadIdx.x;
    const int lane = tid & 31, w = tid >> 5;
    const int wm = w & 3, wn = w >> 2;
    const int rowBase = blockIdx.y * 128;
    const int nBase = blockIdx.x * 128;

    float acc[2][8][4];
#pragma unroll
    for (int i = 0; i < 2; ++i)
#pragma unroll
        for (int j = 0; j < 8; ++j)
#pragma unroll
            for (int e = 0; e < 4; ++e) acc[i][j][e] = 0.0f;

    auto load_stage = [&](int buf, int kc) {
        const int kBase = kc * 64;
        const uint32_t sb = smb + buf * STAGE_B;
#pragma unroll
        for (int it = 0; it < 4; ++it) {
            int idx = tid + it * 256;
            int r = idx >> 3, cc = idx & 7;
            uint32_t so = (uint32_t)(r * 144 + cc * 16);
            size_t goA = (size_t)(rowBase + r) * DDIM + kBase + cc * 8;
            size_t goB = (size_t)(nBase + r) * DDIM + kBase + cc * 8;
            CP16(sb + so,             g_q + goA);
            CP16(sb + ARR_B + so,     g_kh + goB);
            CP16(sb + 2 * ARR_B + so, g_kl + goB);
        }
        CP_COMMIT;
    };

    const uint32_t aOff = (uint32_t)((wm * 32 + (lane & 15)) * 144 + ((lane >> 4) * 8) * 2);
    const int g = lane >> 3;
    const uint32_t bOff = (uint32_t)((wn * 64 + ((g >> 1) << 3) + (lane & 7)) * 144
                                     + ((g & 1) << 3) * 2);

    load_stage(0, 0);

#pragma unroll 1
    for (int c = 0; c < NC; ++c) {
        CP_WAITG(0);
        __syncthreads();
        if (c + 1 < NC) load_stage((c + 1) & 1, c + 1);

        const uint32_t sb = smb + (c & 1) * STAGE_B;
        const uint32_t aA = sb + aOff;
        const uint32_t bH = sb + ARR_B + bOff, bL = sb + 2 * ARR_B + bOff;
#pragma unroll
        for (int kk = 0; kk < 4; ++kk) {
            uint32_t aq[2][4], kh[4][4], kl[4][4];
#pragma unroll
            for (int i = 0; i < 2; ++i)
                LDSM_X4(aq[i][0], aq[i][1], aq[i][2], aq[i][3], aA + i * 2304 + kk * 32);
#pragma unroll
            for (int j = 0; j < 4; ++j) {
                LDSM_X4(kh[j][0], kh[j][1], kh[j][2], kh[j][3], bH + j * 2304 + kk * 32);
                LDSM_X4(kl[j][0], kl[j][1], kl[j][2], kl[j][3], bL + j * 2304 + kk * 32);
            }
#pragma unroll
            for (int i = 0; i < 2; ++i)
#pragma unroll
                for (int jj = 0; jj < 8; ++jj) {
                    MMA_F16(acc[i][jj], aq[i], &kh[jj >> 1][(jj & 1) * 2]);
                    MMA_F16(acc[i][jj], aq[i], &kl[jj >> 1][(jj & 1) * 2]);
                }
        }
    }

    // ---- epilogue: P = exp(acc) -> fp16, plus deterministic row-sum partials
    float ls[2][2] = {{0.0f, 0.0f}, {0.0f, 0.0f}};
#pragma unroll
    for (int i = 0; i < 2; ++i) {
        const int row0 = rowBase + wm * 32 + i * 16 + (lane >> 2);
#pragma unroll
        for (int jj = 0; jj < 8; ++jj) {
            const int col = nBase + wn * 64 + jj * 8 + (lane & 3) * 2;
            float p0 = __expf(acc[i][jj][0]);
            float p1 = __expf(acc[i][jj][1]);
            float p2 = __expf(acc[i][jj][2]);
            float p3 = __expf(acc[i][jj][3]);
            ls[i][0] += p0 + p1;
            ls[i][1] += p2 + p3;
            *(__half2*)&g_p[(size_t)row0 * NKV + col] = __floats2half2_rn(p0, p1);
            *(__half2*)&g_p[(size_t)(row0 + 8) * NKV + col] = __floats2half2_rn(p2, p3);
        }
    }
    const int slot = blockIdx.x * 2 + wn;
#pragma unroll
    for (int i = 0; i < 2; ++i)
#pragma unroll
        for (int pr = 0; pr < 2; ++pr) {
            float s = ls[i][pr];
            s += __shfl_xor_sync(0xffffffffu, s, 1);
            s += __shfl_xor_sync(0xffffffffu, s, 2);
            if ((lane & 3) == 0) {
                int row = rowBase + wm * 32 + i * 16 + (lane >> 2) + pr * 8;
                g_lpart[(size_t)slot * NQ + row] = s;
            }
        }
}

// ---- GEMM2: O = (P V) * linv, K=8192 ----
__global__ __launch_bounds__(256, 2) void gemm2_kernel(float* __restrict__ outp)
{
    constexpr int NC = NKV / 64;    // 128
    extern __shared__ char smc[];
    const uint32_t smb = smem_u32(smc);

    const int tid = threadIdx.x;
    const int lane = tid & 31, w = tid >> 5;
    const int wm = w & 3, wn = w >> 2;
    const int rowBase = blockIdx.y * 128;
    const int nBase = blockIdx.x * 128;

    float acc[2][8][4];
#pragma unroll
    for (int i = 0; i < 2; ++i)
#pragma unroll
        for (int j = 0; j < 8; ++j)
#pragma unroll
            for (int e = 0; e < 4; ++e) acc[i][j][e] = 0.0f;

    auto load_stage = [&](int buf, int kc) {
        const int kBase = kc * 64;
        const uint32_t sb = smb + buf * STAGE_B;
#pragma unroll
        for (int it = 0; it < 4; ++it) {
            int idx = tid + it * 256;
            int r = idx >> 3, cc = idx & 7;
            uint32_t so = (uint32_t)(r * 144 + cc * 16);
            size_t goA = (size_t)(rowBase + r) * NKV + kBase + cc * 8;
            size_t goB = (size_t)(nBase + r) * NKV + kBase + cc * 8;
            CP16(sb + so,             g_p + goA);
            CP16(sb + ARR_B + so,     g_vth + goB);
            CP16(sb + 2 * ARR_B + so, g_vtl + goB);
        }
        CP_COMMIT;
    };

    const uint32_t aOff = (uint32_t)((wm * 32 + (lane & 15)) * 144 + ((lane >> 4) * 8) * 2);
    const int g = lane >> 3;
    const uint32_t bOff = (uint32_t)((wn * 64 + ((g >> 1) << 3) + (lane & 7)) * 144
                                     + ((g & 1) << 3) * 2);

    load_stage(0, 0);

#pragma unroll 1
    for (int c = 0; c < NC; ++c) {
        CP_WAITG(0);
        __syncthreads();
        if (c + 1 < NC) load_stage((c + 1) & 1, c + 1);

        const uint32_t sb = smb + (c & 1) * STAGE_B;
        const uint32_t aP = sb + aOff;
        const uint32_t bH = sb + ARR_B + bOff, bL = sb + 2 * ARR_B + bOff;
#pragma unroll
        for (int kk = 0; kk < 4; ++kk) {
            uint32_t ap[2][4], vh[4][4], vl[4][4];
#pragma unroll
            for (int i = 0; i < 2; ++i)
                LDSM_X4(ap[i][0], ap[i][1], ap[i][2], ap[i][3], aP + i * 2304 + kk * 32);
#pragma unroll
            for (int j = 0; j < 4; ++j) {
                LDSM_X4(vh[j][0], vh[j][1], vh[j][2], vh[j][3], bH + j * 2304 + kk * 32);
                LDSM_X4(vl[j][0], vl[j][1], vl[j][2], vl[j][3], bL + j * 2304 + kk * 32);
            }
#pragma unroll
            for (int i = 0; i < 2; ++i)
#pragma unroll
                for (int jj = 0; jj < 8; ++jj) {
                    MMA_F16(acc[i][jj], ap[i], &vh[jj >> 1][(jj & 1) * 2]);
                    MMA_F16(acc[i][jj], ap[i], &vl[jj >> 1][(jj & 1) * 2]);
                }
        }
    }

    // ---- epilogue: out = acc * linv[row]
#pragma unroll
    for (int i = 0; i < 2; ++i) {
        const int row0 = rowBase + wm * 32 + i * 16 + (lane >> 2);
        const float inv0 = g_linv[row0];
        const float inv1 = g_linv[row0 + 8];
#pragma unroll
        for (int jj = 0; jj < 8; ++jj) {
            const int col = nBase + wn * 64 + jj * 8 + (lane & 3) * 2;
            float2 r0, r1;
            r0.x = acc[i][jj][0] * inv0; r0.y = acc[i][jj][1] * inv0;
            r1.x = acc[i][jj][2] * inv1; r1.y = acc[i][jj][3] * inv1;
            *(float2*)&outp[(size_t)row0 * DDIM + col] = r0;
            *(float2*)&outp[(size_t)(row0 + 8) * DDIM + col] = r1;
        }
    }
}

// ---------------------------------------------------------------------------
__global__ void lred_kernel()
{
    int row = blockIdx.x * 256 + threadIdx.x;
    float s = 0.0f;
#pragma unroll 8
    for (int j = 0; j < 128; ++j) s += g_lpart[(size_t)j * NQ + row];
    g_linv[row] = 1.0f / s;
}

// ---------------------------------------------------------------------------
extern "C" void kernel_launch(void* const* d_in, const int* in_sizes, int n_in,
                              void* d_out, int out_size)
{
    const float* x   = (const float*)d_in[0];
    const float* dom = (const float*)d_in[1];
    const float* Wq  = (const float*)d_in[2];
    const float* bq  = (const float*)d_in[3];
    const float* Wk  = (const float*)d_in[4];
    const float* bk  = (const float*)d_in[5];
    const float* Wv  = (const float*)d_in[6];
    const float* bv  = (const float*)d_in[7];
    float* out = (float*)d_out;

    cudaFuncSetAttribute(gemm1_kernel,
                         cudaFuncAttributeMaxDynamicSharedMemorySize, SMEM_GB);
    cudaFuncSetAttribute(gemm2_kernel,
                         cudaFuncAttributeMaxDynamicSharedMemorySize, SMEM_GB);

    dim3 gproj(DDIM / 128, NQ / 128, 3);
    proj_kernel<<<gproj, 256>>>(x, dom, Wq, bq, Wk, bk, Wv, bv);

    // P = exp(q k^T)
    gemm1_kernel<<<dim3(NKV / 128, NQ / 128), 256, SMEM_GB>>>();

    lred_kernel<<<NQ / 256, 256>>>();

    // O = (P V) * linv
    gemm2_kernel<<<dim3(DDIM / 128, NQ / 128), 256, SMEM_GB>>>(out);
}

// round 11
// speedup vs baseline: 6.5551x; 1.4878x over previous
#include <cuda_runtime.h>
#include <cuda_bf16.h>
#include <cuda_fp16.h>
#include <cstdint>

#define NQ 8192
#define NKV 8192
#define DDIM 512
static constexpr float QSCALE = 0.044194173824159216f; // 1/sqrt(512)

// ---------------- scratch (device globals; no allocation) ----------------
__device__ __align__(256) __half g_q[NQ * DDIM];      // q fp16 (scaled)
__device__ __align__(256) __half g_k[NKV * DDIM];     // k fp16
__device__ __align__(256) __half g_vt[DDIM * NKV];    // V^T fp16 [512, 8192]
__device__ __align__(256) __half g_p[(size_t)NQ * NKV];  // P = exp(scores), fp16
__device__ float g_lpart[128 * NQ];   // [slot][row]
__device__ float g_linv[NQ];

// ---------------- helpers ----------------
__device__ __forceinline__ uint32_t smem_u32(const void* p) {
    uint32_t a;
    asm("{ .reg .u64 t; cvta.to.shared.u64 t, %1; cvt.u32.u64 %0, t; }"
        : "=r"(a) : "l"(p));
    return a;
}

#define CP16(sa, gp) \
    asm volatile("cp.async.cg.shared.global [%0], [%1], 16;" \
                 :: "r"(sa), "l"(gp) : "memory")
#define CP_COMMIT asm volatile("cp.async.commit_group;" ::: "memory")
#define CP_WAITG(n) asm volatile("cp.async.wait_group %0;" :: "n"(n) : "memory")

#define LDSM_X4(r0, r1, r2, r3, addr) \
    asm volatile("ldmatrix.sync.aligned.m8n8.x4.shared.b16 {%0,%1,%2,%3}, [%4];" \
                 : "=r"(r0), "=r"(r1), "=r"(r2), "=r"(r3) : "r"(addr))

#define MMA_F16(d, a, b) \
    asm volatile("mma.sync.aligned.m16n8k16.row.col.f32.f16.f16.f32 " \
                 "{%0,%1,%2,%3}, {%4,%5,%6,%7}, {%8,%9}, {%0,%1,%2,%3};" \
                 : "+f"((d)[0]), "+f"((d)[1]), "+f"((d)[2]), "+f"((d)[3]) \
                 : "r"((a)[0]), "r"((a)[1]), "r"((a)[2]), "r"((a)[3]), \
                   "r"((b)[0]), "r"((b)[1]))

// ---------------------------------------------------------------------------
// Projection (fp32 FFMA, 128x128 tile) -> fp16 q (scaled), k, V^T.
// ---------------------------------------------------------------------------
__global__ __launch_bounds__(256) void proj_kernel(
    const float* __restrict__ x, const float* __restrict__ dom,
    const float* __restrict__ Wq, const float* __restrict__ bq,
    const float* __restrict__ Wk, const float* __restrict__ bk,
    const float* __restrict__ Wv, const float* __restrict__ bv)
{
    __shared__ float As[16][132];
    __shared__ float Bs[16][132];

    const int z = blockIdx.z;
    const float* A = (z == 0) ? x : dom;
    const float* W = (z == 0) ? Wq : (z == 1 ? Wk : Wv);
    const float* b = (z == 0) ? bq : (z == 1 ? bk : bv);
    const float scale = (z == 0) ? QSCALE : 1.0f;

    const int tid = threadIdx.x;
    const int tx = tid & 15, ty = tid >> 4;
    const int rowBase = blockIdx.y * 128;
    const int colBase = blockIdx.x * 128;

    float acc[8][8];
#pragma unroll
    for (int i = 0; i < 8; ++i)
#pragma unroll
        for (int j = 0; j < 8; ++j) acc[i][j] = 0.0f;

    for (int kt = 0; kt < DDIM / 16; ++kt) {
        const int k0 = kt * 16;
#pragma unroll
        for (int it = 0; it < 2; ++it) {
            int idx = tid + 256 * it;
            int r = idx >> 2, c4 = idx & 3;
            float4 a = *(const float4*)&A[(size_t)(rowBase + r) * DDIM + k0 + c4 * 4];
            As[c4 * 4 + 0][r] = a.x; As[c4 * 4 + 1][r] = a.y;
            As[c4 * 4 + 2][r] = a.z; As[c4 * 4 + 3][r] = a.w;
            float4 w = *(const float4*)&W[(size_t)(colBase + r) * DDIM + k0 + c4 * 4];
            Bs[c4 * 4 + 0][r] = w.x; Bs[c4 * 4 + 1][r] = w.y;
            Bs[c4 * 4 + 2][r] = w.z; Bs[c4 * 4 + 3][r] = w.w;
        }
        __syncthreads();
#pragma unroll
        for (int k = 0; k < 16; ++k) {
            float ar[8], br[8];
            *(float4*)&ar[0] = *(const float4*)&As[k][ty * 8];
            *(float4*)&ar[4] = *(const float4*)&As[k][ty * 8 + 4];
            *(float4*)&br[0] = *(const float4*)&Bs[k][tx * 8];
            *(float4*)&br[4] = *(const float4*)&Bs[k][tx * 8 + 4];
#pragma unroll
            for (int i = 0; i < 8; ++i)
#pragma unroll
                for (int j = 0; j < 8; ++j) acc[i][j] += ar[i] * br[j];
        }
        __syncthreads();
    }

    if (z == 2) {
        // V^T fp16: vt[col][row], rows contiguous
#pragma unroll
        for (int j = 0; j < 8; ++j) {
            int col = colBase + tx * 8 + j;
            float bias = b[col];
            __align__(16) __half hb[8];
#pragma unroll
            for (int i = 0; i < 8; ++i) hb[i] = __float2half_rn(acc[i][j] + bias);
            size_t off = (size_t)col * NKV + rowBase + ty * 8;
            *(uint4*)&g_vt[off] = *(uint4*)hb;
        }
    } else {
        __half* dst = z ? g_k : g_q;
#pragma unroll
        for (int i = 0; i < 8; ++i) {
            int row = rowBase + ty * 8 + i;
            __align__(16) __half hb[8];
#pragma unroll
            for (int e = 0; e < 8; ++e) {
                int col = colBase + tx * 8 + e;
                hb[e] = __float2half_rn((acc[i][e] + b[col]) * scale);
            }
            size_t off = (size_t)row * DDIM + colBase + tx * 8;
            *(uint4*)&dst[off] = *(uint4*)hb;
        }
    }
}

// ---------------------------------------------------------------------------
// GEMM geometry: 128x128 block tile, 8 warps (4m x 2n), warp 32x64, BK=64,
// SMEM rows padded to 144B, 3-stage cp.async pipeline, 2 CTAs/SM.
// Single fp16 MMA product.
// ---------------------------------------------------------------------------
#define ARR_B    18432           // 128 rows * 144 B
#define STAGE_B  (2 * ARR_B)     // A | B
#define SMEM_GB  (3 * STAGE_B)   // 110592

// ---- GEMM1: P = exp(q k^T), K=512 ----
__global__ __launch_bounds__(256, 2) void gemm1_kernel()
{
    constexpr int NC = DDIM / 64;   // 8
    extern __shared__ char smc[];
    const uint32_t smb = smem_u32(smc);

    const int tid = threadIdx.x;
    const int lane = tid & 31, w = tid >> 5;
    const int wm = w & 3, wn = w >> 2;
    const int rowBase = blockIdx.y * 128;
    const int nBase = blockIdx.x * 128;

    float acc[2][8][4];
#pragma unroll
    for (int i = 0; i < 2; ++i)
#pragma unroll
        for (int j = 0; j < 8; ++j)
#pragma unroll
            for (int e = 0; e < 4; ++e) acc[i][j][e] = 0.0f;

    auto load_stage = [&](int buf, int kc) {
        const int kBase = kc * 64;
        const uint32_t sb = smb + buf * STAGE_B;
#pragma unroll
        for (int it = 0; it < 4; ++it) {
            int idx = tid + it * 256;
            int r = idx >> 3, cc = idx & 7;
            uint32_t so = (uint32_t)(r * 144 + cc * 16);
            CP16(sb + so,         g_q + (size_t)(rowBase + r) * DDIM + kBase + cc * 8);
            CP16(sb + ARR_B + so, g_k + (size_t)(nBase + r) * DDIM + kBase + cc * 8);
        }
        CP_COMMIT;
    };

    const uint32_t aOff = (uint32_t)((wm * 32 + (lane & 15)) * 144 + ((lane >> 4) * 8) * 2);
    const int g = lane >> 3;
    const uint32_t bOff = (uint32_t)((wn * 64 + ((g >> 1) << 3) + (lane & 7)) * 144
                                     + ((g & 1) << 3) * 2);

    load_stage(0, 0);
    load_stage(1, 1);

#pragma unroll 1
    for (int c = 0; c < NC; ++c) {
        if (c == NC - 1) { CP_WAITG(0); } else { CP_WAITG(1); }
        __syncthreads();
        if (c + 2 < NC) load_stage((c + 2) % 3, c + 2);

        const uint32_t sb = smb + (c % 3) * STAGE_B;
        const uint32_t aA = sb + aOff;
        const uint32_t bB = sb + ARR_B + bOff;
#pragma unroll
        for (int kk = 0; kk < 4; ++kk) {
            uint32_t aq[2][4], kb[4][4];
#pragma unroll
            for (int i = 0; i < 2; ++i)
                LDSM_X4(aq[i][0], aq[i][1], aq[i][2], aq[i][3], aA + i * 2304 + kk * 32);
#pragma unroll
            for (int j = 0; j < 4; ++j)
                LDSM_X4(kb[j][0], kb[j][1], kb[j][2], kb[j][3], bB + j * 2304 + kk * 32);
#pragma unroll
            for (int i = 0; i < 2; ++i)
#pragma unroll
                for (int jj = 0; jj < 8; ++jj)
                    MMA_F16(acc[i][jj], aq[i], &kb[jj >> 1][(jj & 1) * 2]);
        }
    }

    // ---- epilogue: P = exp(acc) -> fp16, plus deterministic row-sum partials
    float ls[2][2] = {{0.0f, 0.0f}, {0.0f, 0.0f}};
#pragma unroll
    for (int i = 0; i < 2; ++i) {
        const int row0 = rowBase + wm * 32 + i * 16 + (lane >> 2);
#pragma unroll
        for (int jj = 0; jj < 8; ++jj) {
            const int col = nBase + wn * 64 + jj * 8 + (lane & 3) * 2;
            float p0 = __expf(acc[i][jj][0]);
            float p1 = __expf(acc[i][jj][1]);
            float p2 = __expf(acc[i][jj][2]);
            float p3 = __expf(acc[i][jj][3]);
            ls[i][0] += p0 + p1;
            ls[i][1] += p2 + p3;
            *(__half2*)&g_p[(size_t)row0 * NKV + col] = __floats2half2_rn(p0, p1);
            *(__half2*)&g_p[(size_t)(row0 + 8) * NKV + col] = __floats2half2_rn(p2, p3);
        }
    }
    const int slot = blockIdx.x * 2 + wn;
#pragma unroll
    for (int i = 0; i < 2; ++i)
#pragma unroll
        for (int pr = 0; pr < 2; ++pr) {
            float s = ls[i][pr];
            s += __shfl_xor_sync(0xffffffffu, s, 1);
            s += __shfl_xor_sync(0xffffffffu, s, 2);
            if ((lane & 3) == 0) {
                int row = rowBase + wm * 32 + i * 16 + (lane >> 2) + pr * 8;
                g_lpart[(size_t)slot * NQ + row] = s;
            }
        }
}

// ---- GEMM2: O = (P V) * linv, K=8192 ----
__global__ __launch_bounds__(256, 2) void gemm2_kernel(float* __restrict__ outp)
{
    constexpr int NC = NKV / 64;    // 128
    extern __shared__ char smc[];
    const uint32_t smb = smem_u32(smc);

    const int tid = threadIdx.x;
    const int lane = tid & 31, w = tid >> 5;
    const int wm = w & 3, wn = w >> 2;
    const int rowBase = blockIdx.y * 128;
    const int nBase = blockIdx.x * 128;

    float acc[2][8][4];
#pragma unroll
    for (int i = 0; i < 2; ++i)
#pragma unroll
        for (int j = 0; j < 8; ++j)
#pragma unroll
            for (int e = 0; e < 4; ++e) acc[i][j][e] = 0.0f;

    auto load_stage = [&](int buf, int kc) {
        const int kBase = kc * 64;
        const uint32_t sb = smb + buf * STAGE_B;
#pragma unroll
        for (int it = 0; it < 4; ++it) {
            int idx = tid + it * 256;
            int r = idx >> 3, cc = idx & 7;
            uint32_t so = (uint32_t)(r * 144 + cc * 16);
            CP16(sb + so,         g_p + (size_t)(rowBase + r) * NKV + kBase + cc * 8);
            CP16(sb + ARR_B + so, g_vt + (size_t)(nBase + r) * NKV + kBase + cc * 8);
        }
        CP_COMMIT;
    };

    const uint32_t aOff = (uint32_t)((wm * 32 + (lane & 15)) * 144 + ((lane >> 4) * 8) * 2);
    const int g = lane >> 3;
    const uint32_t bOff = (uint32_t)((wn * 64 + ((g >> 1) << 3) + (lane & 7)) * 144
                                     + ((g & 1) << 3) * 2);

    load_stage(0, 0);
    load_stage(1, 1);

#pragma unroll 1
    for (int c = 0; c < NC; ++c) {
        if (c == NC - 1) { CP_WAITG(0); } else { CP_WAITG(1); }
        __syncthreads();
        if (c + 2 < NC) load_stage((c + 2) % 3, c + 2);

        const uint32_t sb = smb + (c % 3) * STAGE_B;
        const uint32_t aP = sb + aOff;
        const uint32_t bV = sb + ARR_B + bOff;
#pragma unroll
        for (int kk = 0; kk < 4; ++kk) {
            uint32_t ap[2][4], vb[4][4];
#pragma unroll
            for (int i = 0; i < 2; ++i)
                LDSM_X4(ap[i][0], ap[i][1], ap[i][2], ap[i][3], aP + i * 2304 + kk * 32);
#pragma unroll
            for (int j = 0; j < 4; ++j)
                LDSM_X4(vb[j][0], vb[j][1], vb[j][2], vb[j][3], bV + j * 2304 + kk * 32);
#pragma unroll
            for (int i = 0; i < 2; ++i)
#pragma unroll
                for (int jj = 0; jj < 8; ++jj)
                    MMA_F16(acc[i][jj], ap[i], &vb[jj >> 1][(jj & 1) * 2]);
        }
    }

    // ---- epilogue: out = acc * linv[row]
#pragma unroll
    for (int i = 0; i < 2; ++i) {
        const int row0 = rowBase + wm * 32 + i * 16 + (lane >> 2);
        const float inv0 = g_linv[row0];
        const float inv1 = g_linv[row0 + 8];
#pragma unroll
        for (int jj = 0; jj < 8; ++jj) {
            const int col = nBase + wn * 64 + jj * 8 + (lane & 3) * 2;
            float2 r0, r1;
            r0.x = acc[i][jj][0] * inv0; r0.y = acc[i][jj][1] * inv0;
            r1.x = acc[i][jj][2] * inv1; r1.y = acc[i][jj][3] * inv1;
            *(float2*)&outp[(size_t)row0 * DDIM + col] = r0;
            *(float2*)&outp[(size_t)(row0 + 8) * DDIM + col] = r1;
        }
    }
}

// ---------------------------------------------------------------------------
__global__ void lred_kernel()
{
    int row = blockIdx.x * 256 + threadIdx.x;
    float s = 0.0f;
#pragma unroll 8
    for (int j = 0; j < 128; ++j) s += g_lpart[(size_t)j * NQ + row];
    g_linv[row] = 1.0f / s;
}

// ---------------------------------------------------------------------------
extern "C" void kernel_launch(void* const* d_in, const int* in_sizes, int n_in,
                              void* d_out, int out_size)
{
    const float* x   = (const float*)d_in[0];
    const float* dom = (const float*)d_in[1];
    const float* Wq  = (const float*)d_in[2];
    const float* bq  = (const float*)d_in[3];
    const float* Wk  = (const float*)d_in[4];
    const float* bk  = (const float*)d_in[5];
    const float* Wv  = (const float*)d_in[6];
    const float* bv  = (const float*)d_in[7];
    float* out = (float*)d_out;

    cudaFuncSetAttribute(gemm1_kernel,
                         cudaFuncAttributeMaxDynamicSharedMemorySize, SMEM_GB);
    cudaFuncSetAttribute(gemm2_kernel,
                         cudaFuncAttributeMaxDynamicSharedMemorySize, SMEM_GB);

    dim3 gproj(DDIM / 128, NQ / 128, 3);
    proj_kernel<<<gproj, 256>>>(x, dom, Wq, bq, Wk, bk, Wv, bv);

    // P = exp(q k^T)
    gemm1_kernel<<<dim3(NKV / 128, NQ / 128), 256, SMEM_GB>>>();

    lred_kernel<<<NQ / 256, 256>>>();

    // O = (P V) * linv
    gemm2_kernel<<<dim3(DDIM / 128, NQ / 128), 256, SMEM_GB>>>(out);
}

// round 12
// speedup vs baseline: 9.3332x; 1.4238x over previous
#include <cuda_runtime.h>
#include <cuda_bf16.h>
#include <cuda_fp16.h>
#include <cstdint>

#define NQ 8192
#define NKV 8192
#define DDIM 512
static constexpr float QSCALE = 0.044194173824159216f; // 1/sqrt(512)

// ---------------- scratch (device globals; no allocation) ----------------
__device__ __align__(256) __half g_xh[NQ * DDIM];     // x fp16
__device__ __align__(256) __half g_domh[NKV * DDIM];  // dom hi
__device__ __align__(256) __half g_doml[NKV * DDIM];  // dom lo
__device__ __align__(256) __half g_wqh[DDIM * DDIM], g_wql[DDIM * DDIM];
__device__ __align__(256) __half g_wkh[DDIM * DDIM], g_wkl[DDIM * DDIM];
__device__ __align__(256) __half g_wvh[DDIM * DDIM];

__device__ __align__(256) __half g_q[NQ * DDIM];      // q fp16 (scaled)
__device__ __align__(256) __half g_k[NKV * DDIM];     // k fp16
__device__ __align__(256) __half g_vt[DDIM * NKV];    // V^T fp16 [512, 8192]
__device__ __align__(256) __half g_p[(size_t)NQ * NKV];  // P = exp(scores), fp16
__device__ float g_lpart[128 * NQ];   // [slot][row]
__device__ float g_linv[NQ];

// ---------------- helpers ----------------
__device__ __forceinline__ uint32_t smem_u32(const void* p) {
    uint32_t a;
    asm("{ .reg .u64 t; cvta.to.shared.u64 t, %1; cvt.u32.u64 %0, t; }"
        : "=r"(a) : "l"(p));
    return a;
}

#define CP16(sa, gp) \
    asm volatile("cp.async.cg.shared.global [%0], [%1], 16;" \
                 :: "r"(sa), "l"(gp) : "memory")
#define CP_COMMIT asm volatile("cp.async.commit_group;" ::: "memory")
#define CP_WAITG(n) asm volatile("cp.async.wait_group %0;" :: "n"(n) : "memory")

#define LDSM_X4(r0, r1, r2, r3, addr) \
    asm volatile("ldmatrix.sync.aligned.m8n8.x4.shared.b16 {%0,%1,%2,%3}, [%4];" \
                 : "=r"(r0), "=r"(r1), "=r"(r2), "=r"(r3) : "r"(addr))

#define MMA_F16(d, a, b) \
    asm volatile("mma.sync.aligned.m16n8k16.row.col.f32.f16.f16.f32 " \
                 "{%0,%1,%2,%3}, {%4,%5,%6,%7}, {%8,%9}, {%0,%1,%2,%3};" \
                 : "+f"((d)[0]), "+f"((d)[1]), "+f"((d)[2]), "+f"((d)[3]) \
                 : "r"((a)[0]), "r"((a)[1]), "r"((a)[2]), "r"((a)[3]), \
                   "r"((b)[0]), "r"((b)[1]))

__device__ __forceinline__ uint2 pack4h(float a, float b, float c, float d) {
    uint2 r;
    __half2 lo = __floats2half2_rn(a, b), hi = __floats2half2_rn(c, d);
    r.x = *(uint32_t*)&lo; r.y = *(uint32_t*)&hi;
    return r;
}

// ---------------------------------------------------------------------------
// presplit: fp32 -> fp16 (and hi/lo splits). 1M threads, 4 floats each.
// ---------------------------------------------------------------------------
__global__ __launch_bounds__(256) void presplit_kernel(
    const float* __restrict__ x, const float* __restrict__ dom,
    const float* __restrict__ Wq, const float* __restrict__ Wk,
    const float* __restrict__ Wv)
{
    const int i = blockIdx.x * 256 + threadIdx.x;   // 0 .. 1048575

    {   // x -> xh (single)
        float4 v = ((const float4*)x)[i];
        ((uint2*)g_xh)[i] = pack4h(v.x, v.y, v.z, v.w);
    }
    {   // dom -> hi/lo
        float4 v = ((const float4*)dom)[i];
        __half h0 = __float2half_rn(v.x), h1 = __float2half_rn(v.y);
        __half h2 = __float2half_rn(v.z), h3 = __float2half_rn(v.w);
        uint2 hh; __half2 p01 = __halves2half2(h0, h1), p23 = __halves2half2(h2, h3);
        hh.x = *(uint32_t*)&p01; hh.y = *(uint32_t*)&p23;
        ((uint2*)g_domh)[i] = hh;
        ((uint2*)g_doml)[i] = pack4h(v.x - __half2float(h0), v.y - __half2float(h1),
                                     v.z - __half2float(h2), v.w - __half2float(h3));
    }
    if (i < (DDIM * DDIM) / 4) {
        {   // Wq hi/lo
            float4 v = ((const float4*)Wq)[i];
            __half h0 = __float2half_rn(v.x), h1 = __float2half_rn(v.y);
            __half h2 = __float2half_rn(v.z), h3 = __float2half_rn(v.w);
            uint2 hh; __half2 p01 = __halves2half2(h0, h1), p23 = __halves2half2(h2, h3);
            hh.x = *(uint32_t*)&p01; hh.y = *(uint32_t*)&p23;
            ((uint2*)g_wqh)[i] = hh;
            ((uint2*)g_wql)[i] = pack4h(v.x - __half2float(h0), v.y - __half2float(h1),
                                        v.z - __half2float(h2), v.w - __half2float(h3));
        }
        {   // Wk hi/lo
            float4 v = ((const float4*)Wk)[i];
            __half h0 = __float2half_rn(v.x), h1 = __float2half_rn(v.y);
            __half h2 = __float2half_rn(v.z), h3 = __float2half_rn(v.w);
            uint2 hh; __half2 p01 = __halves2half2(h0, h1), p23 = __halves2half2(h2, h3);
            hh.x = *(uint32_t*)&p01; hh.y = *(uint32_t*)&p23;
            ((uint2*)g_wkh)[i] = hh;
            ((uint2*)g_wkl)[i] = pack4h(v.x - __half2float(h0), v.y - __half2float(h1),
                                        v.z - __half2float(h2), v.w - __half2float(h3));
        }
        {   // Wv hi only
            float4 v = ((const float4*)Wv)[i];
            ((uint2*)g_wvh)[i] = pack4h(v.x, v.y, v.z, v.w);
        }
    }
}

// ---------------------------------------------------------------------------
// GEMM geometry: 128x128 block tile, 8 warps (4m x 2n), warp 32x64, BK=64,
// SMEM rows padded to 144B, 2 CTAs/SM.
// ---------------------------------------------------------------------------
#define ARR_B    18432           // 128 rows * 144 B
#define STAGE2_B (2 * ARR_B)     // A | B          (gemm1 / gemm2, 3-stage)
#define SMEM_GB  (3 * STAGE2_B)  // 110592
#define STAGE3_B (3 * ARR_B)     // A | Bh | Bl    (proj, 2-stage)
#define SMEM_PJ  (2 * STAGE3_B)  // 110592

// ---------------------------------------------------------------------------
// proj_gemm: 2-product fp16. blockIdx.z selects:
//   z=0: q  = (xh @ Wq^T + bq) * QSCALE       [8192,512]
//   z=1: k  =  domh @ Wk^T + bk               [8192,512]
//   z=2: vt =  Wvh @ dom^T + bv (per-row)     [512,8192]  (V^T directly)
// ---------------------------------------------------------------------------
__global__ __launch_bounds__(256, 2) void proj_gemm_kernel(
    const float* __restrict__ bq, const float* __restrict__ bk,
    const float* __restrict__ bv)
{
    constexpr int NC = DDIM / 64;   // 8
    extern __shared__ char smc[];
    const uint32_t smb = smem_u32(smc);

    const int mode = blockIdx.z;
    const int bx = (mode == 2) ? blockIdx.x : blockIdx.y;   // n tile
    const int by = (mode == 2) ? blockIdx.y : blockIdx.x;   // m tile

    const __half* __restrict__ A  = (mode == 0) ? g_xh  : (mode == 1 ? g_domh : g_wvh);
    const __half* __restrict__ Bh = (mode == 0) ? g_wqh : (mode == 1 ? g_wkh : g_domh);
    const __half* __restrict__ Bl = (mode == 0) ? g_wql : (mode == 1 ? g_wkl : g_doml);
    const float* __restrict__ bias = (mode == 0) ? bq : (mode == 1 ? bk : bv);
    __half* __restrict__ outp = (mode == 0) ? g_q : (mode == 1 ? g_k : g_vt);
    const int outLD = (mode == 2) ? NKV : DDIM;
    const float scale = (mode == 0) ? QSCALE : 1.0f;

    const int tid = threadIdx.x;
    const int lane = tid & 31, w = tid >> 5;
    const int wm = w & 3, wn = w >> 2;
    const int rowBase = by * 128;
    const int nBase = bx * 128;

    float acc[2][8][4];
#pragma unroll
    for (int i = 0; i < 2; ++i)
#pragma unroll
        for (int j = 0; j < 8; ++j)
#pragma unroll
            for (int e = 0; e < 4; ++e) acc[i][j][e] = 0.0f;

    auto load_stage = [&](int buf, int kc) {
        const int kBase = kc * 64;
        const uint32_t sb = smb + buf * STAGE3_B;
#pragma unroll
        for (int it = 0; it < 4; ++it) {
            int idx = tid + it * 256;
            int r = idx >> 3, cc = idx & 7;
            uint32_t so = (uint32_t)(r * 144 + cc * 16);
            size_t goA = (size_t)(rowBase + r) * DDIM + kBase + cc * 8;
            size_t goB = (size_t)(nBase + r) * DDIM + kBase + cc * 8;
            CP16(sb + so,             A  + goA);
            CP16(sb + ARR_B + so,     Bh + goB);
            CP16(sb + 2 * ARR_B + so, Bl + goB);
        }
        CP_COMMIT;
    };

    const uint32_t aOff = (uint32_t)((wm * 32 + (lane & 15)) * 144 + ((lane >> 4) * 8) * 2);
    const int g = lane >> 3;
    const uint32_t bOff = (uint32_t)((wn * 64 + ((g >> 1) << 3) + (lane & 7)) * 144
                                     + ((g & 1) << 3) * 2);

    load_stage(0, 0);

#pragma unroll 1
    for (int c = 0; c < NC; ++c) {
        CP_WAITG(0);
        __syncthreads();
        if (c + 1 < NC) load_stage((c + 1) & 1, c + 1);

        const uint32_t sb = smb + (c & 1) * STAGE3_B;
        const uint32_t aA = sb + aOff;
        const uint32_t bH = sb + ARR_B + bOff, bL = sb + 2 * ARR_B + bOff;
#pragma unroll
        for (int kk = 0; kk < 4; ++kk) {
            uint32_t av[2][4], bh[4][4], bl[4][4];
#pragma unroll
            for (int i = 0; i < 2; ++i)
                LDSM_X4(av[i][0], av[i][1], av[i][2], av[i][3], aA + i * 2304 + kk * 32);
#pragma unroll
            for (int j = 0; j < 4; ++j) {
                LDSM_X4(bh[j][0], bh[j][1], bh[j][2], bh[j][3], bH + j * 2304 + kk * 32);
                LDSM_X4(bl[j][0], bl[j][1], bl[j][2], bl[j][3], bL + j * 2304 + kk * 32);
            }
#pragma unroll
            for (int i = 0; i < 2; ++i)
#pragma unroll
                for (int jj = 0; jj < 8; ++jj) {
                    MMA_F16(acc[i][jj], av[i], &bh[jj >> 1][(jj & 1) * 2]);
                    MMA_F16(acc[i][jj], av[i], &bl[jj >> 1][(jj & 1) * 2]);
                }
        }
    }

    // ---- epilogue: bias (+scale) -> fp16 store ----
    if (mode == 2) {
#pragma unroll
        for (int i = 0; i < 2; ++i) {
            const int row0 = rowBase + wm * 32 + i * 16 + (lane >> 2);
            const float b0 = bias[row0], b1 = bias[row0 + 8];
#pragma unroll
            for (int jj = 0; jj < 8; ++jj) {
                const int col = nBase + wn * 64 + jj * 8 + (lane & 3) * 2;
                *(__half2*)&outp[(size_t)row0 * outLD + col] =
                    __floats2half2_rn(acc[i][jj][0] + b0, acc[i][jj][1] + b0);
                *(__half2*)&outp[(size_t)(row0 + 8) * outLD + col] =
                    __floats2half2_rn(acc[i][jj][2] + b1, acc[i][jj][3] + b1);
            }
        }
    } else {
#pragma unroll
        for (int i = 0; i < 2; ++i) {
            const int row0 = rowBase + wm * 32 + i * 16 + (lane >> 2);
#pragma unroll
            for (int jj = 0; jj < 8; ++jj) {
                const int col = nBase + wn * 64 + jj * 8 + (lane & 3) * 2;
                const float bc0 = bias[col], bc1 = bias[col + 1];
                *(__half2*)&outp[(size_t)row0 * outLD + col] =
                    __floats2half2_rn((acc[i][jj][0] + bc0) * scale,
                                      (acc[i][jj][1] + bc1) * scale);
                *(__half2*)&outp[(size_t)(row0 + 8) * outLD + col] =
                    __floats2half2_rn((acc[i][jj][2] + bc0) * scale,
                                      (acc[i][jj][3] + bc1) * scale);
            }
        }
    }
}

// ---- GEMM1: P = exp(q k^T), K=512, single product, 3-stage ----
__global__ __launch_bounds__(256, 2) void gemm1_kernel()
{
    constexpr int NC = DDIM / 64;   // 8
    extern __shared__ char smc[];
    const uint32_t smb = smem_u32(smc);

    const int tid = threadIdx.x;
    const int lane = tid & 31, w = tid >> 5;
    const int wm = w & 3, wn = w >> 2;
    const int rowBase = blockIdx.y * 128;
    const int nBase = blockIdx.x * 128;

    float acc[2][8][4];
#pragma unroll
    for (int i = 0; i < 2; ++i)
#pragma unroll
        for (int j = 0; j < 8; ++j)
#pragma unroll
            for (int e = 0; e < 4; ++e) acc[i][j][e] = 0.0f;

    auto load_stage = [&](int buf, int kc) {
        const int kBase = kc * 64;
        const uint32_t sb = smb + buf * STAGE2_B;
#pragma unroll
        for (int it = 0; it < 4; ++it) {
            int idx = tid + it * 256;
            int r = idx >> 3, cc = idx & 7;
            uint32_t so = (uint32_t)(r * 144 + cc * 16);
            CP16(sb + so,         g_q + (size_t)(rowBase + r) * DDIM + kBase + cc * 8);
            CP16(sb + ARR_B + so, g_k + (size_t)(nBase + r) * DDIM + kBase + cc * 8);
        }
        CP_COMMIT;
    };

    const uint32_t aOff = (uint32_t)((wm * 32 + (lane & 15)) * 144 + ((lane >> 4) * 8) * 2);
    const int g = lane >> 3;
    const uint32_t bOff = (uint32_t)((wn * 64 + ((g >> 1) << 3) + (lane & 7)) * 144
                                     + ((g & 1) << 3) * 2);

    load_stage(0, 0);
    load_stage(1, 1);

#pragma unroll 1
    for (int c = 0; c < NC; ++c) {
        if (c == NC - 1) { CP_WAITG(0); } else { CP_WAITG(1); }
        __syncthreads();
        if (c + 2 < NC) load_stage((c + 2) % 3, c + 2);

        const uint32_t sb = smb + (c % 3) * STAGE2_B;
        const uint32_t aA = sb + aOff;
        const uint32_t bB = sb + ARR_B + bOff;
#pragma unroll
        for (int kk = 0; kk < 4; ++kk) {
            uint32_t aq[2][4], kb[4][4];
#pragma unroll
            for (int i = 0; i < 2; ++i)
                LDSM_X4(aq[i][0], aq[i][1], aq[i][2], aq[i][3], aA + i * 2304 + kk * 32);
#pragma unroll
            for (int j = 0; j < 4; ++j)
                LDSM_X4(kb[j][0], kb[j][1], kb[j][2], kb[j][3], bB + j * 2304 + kk * 32);
#pragma unroll
            for (int i = 0; i < 2; ++i)
#pragma unroll
                for (int jj = 0; jj < 8; ++jj)
                    MMA_F16(acc[i][jj], aq[i], &kb[jj >> 1][(jj & 1) * 2]);
        }
    }

    // ---- epilogue: P = exp(acc) -> fp16, plus deterministic row-sum partials
    float ls[2][2] = {{0.0f, 0.0f}, {0.0f, 0.0f}};
#pragma unroll
    for (int i = 0; i < 2; ++i) {
        const int row0 = rowBase + wm * 32 + i * 16 + (lane >> 2);
#pragma unroll
        for (int jj = 0; jj < 8; ++jj) {
            const int col = nBase + wn * 64 + jj * 8 + (lane & 3) * 2;
            float p0 = __expf(acc[i][jj][0]);
            float p1 = __expf(acc[i][jj][1]);
            float p2 = __expf(acc[i][jj][2]);
            float p3 = __expf(acc[i][jj][3]);
            ls[i][0] += p0 + p1;
            ls[i][1] += p2 + p3;
            *(__half2*)&g_p[(size_t)row0 * NKV + col] = __floats2half2_rn(p0, p1);
            *(__half2*)&g_p[(size_t)(row0 + 8) * NKV + col] = __floats2half2_rn(p2, p3);
        }
    }
    const int slot = blockIdx.x * 2 + wn;
#pragma unroll
    for (int i = 0; i < 2; ++i)
#pragma unroll
        for (int pr = 0; pr < 2; ++pr) {
            float s = ls[i][pr];
            s += __shfl_xor_sync(0xffffffffu, s, 1);
            s += __shfl_xor_sync(0xffffffffu, s, 2);
            if ((lane & 3) == 0) {
                int row = rowBase + wm * 32 + i * 16 + (lane >> 2) + pr * 8;
                g_lpart[(size_t)slot * NQ + row] = s;
            }
        }
}

// ---- GEMM2: O = (P V) * linv, K=8192, single product, 3-stage ----
__global__ __launch_bounds__(256, 2) void gemm2_kernel(float* __restrict__ outp)
{
    constexpr int NC = NKV / 64;    // 128
    extern __shared__ char smc[];
    const uint32_t smb = smem_u32(smc);

    const int tid = threadIdx.x;
    const int lane = tid & 31, w = tid >> 5;
    const int wm = w & 3, wn = w >> 2;
    const int rowBase = blockIdx.y * 128;
    const int nBase = blockIdx.x * 128;

    float acc[2][8][4];
#pragma unroll
    for (int i = 0; i < 2; ++i)
#pragma unroll
        for (int j = 0; j < 8; ++j)
#pragma unroll
            for (int e = 0; e < 4; ++e) acc[i][j][e] = 0.0f;

    auto load_stage = [&](int buf, int kc) {
        const int kBase = kc * 64;
        const uint32_t sb = smb + buf * STAGE2_B;
#pragma unroll
        for (int it = 0; it < 4; ++it) {
            int idx = tid + it * 256;
            int r = idx >> 3, cc = idx & 7;
            uint32_t so = (uint32_t)(r * 144 + cc * 16);
            CP16(sb + so,         g_p + (size_t)(rowBase + r) * NKV + kBase + cc * 8);
            CP16(sb + ARR_B + so, g_vt + (size_t)(nBase + r) * NKV + kBase + cc * 8);
        }
        CP_COMMIT;
    };

    const uint32_t aOff = (uint32_t)((wm * 32 + (lane & 15)) * 144 + ((lane >> 4) * 8) * 2);
    const int g = lane >> 3;
    const uint32_t bOff = (uint32_t)((wn * 64 + ((g >> 1) << 3) + (lane & 7)) * 144
                                     + ((g & 1) << 3) * 2);

    load_stage(0, 0);
    load_stage(1, 1);

#pragma unroll 1
    for (int c = 0; c < NC; ++c) {
        if (c == NC - 1) { CP_WAITG(0); } else { CP_WAITG(1); }
        __syncthreads();
        if (c + 2 < NC) load_stage((c + 2) % 3, c + 2);

        const uint32_t sb = smb + (c % 3) * STAGE2_B;
        const uint32_t aP = sb + aOff;
        const uint32_t bV = sb + ARR_B + bOff;
#pragma unroll
        for (int kk = 0; kk < 4; ++kk) {
            uint32_t ap[2][4], vb[4][4];
#pragma unroll
            for (int i = 0; i < 2; ++i)
                LDSM_X4(ap[i][0], ap[i][1], ap[i][2], ap[i][3], aP + i * 2304 + kk * 32);
#pragma unroll
            for (int j = 0; j < 4; ++j)
                LDSM_X4(vb[j][0], vb[j][1], vb[j][2], vb[j][3], bV + j * 2304 + kk * 32);
#pragma unroll
            for (int i = 0; i < 2; ++i)
#pragma unroll
                for (int jj = 0; jj < 8; ++jj)
                    MMA_F16(acc[i][jj], ap[i], &vb[jj >> 1][(jj & 1) * 2]);
        }
    }

    // ---- epilogue: out = acc * linv[row]
#pragma unroll
    for (int i = 0; i < 2; ++i) {
        const int row0 = rowBase + wm * 32 + i * 16 + (lane >> 2);
        const float inv0 = g_linv[row0];
        const float inv1 = g_linv[row0 + 8];
#pragma unroll
        for (int jj = 0; jj < 8; ++jj) {
            const int col = nBase + wn * 64 + jj * 8 + (lane & 3) * 2;
            float2 r0, r1;
            r0.x = acc[i][jj][0] * inv0; r0.y = acc[i][jj][1] * inv0;
            r1.x = acc[i][jj][2] * inv1; r1.y = acc[i][jj][3] * inv1;
            *(float2*)&outp[(size_t)row0 * DDIM + col] = r0;
            *(float2*)&outp[(size_t)(row0 + 8) * DDIM + col] = r1;
        }
    }
}

// ---------------------------------------------------------------------------
__global__ void lred_kernel()
{
    int row = blockIdx.x * 256 + threadIdx.x;
    float s = 0.0f;
#pragma unroll 8
    for (int j = 0; j < 128; ++j) s += g_lpart[(size_t)j * NQ + row];
    g_linv[row] = 1.0f / s;
}

// ---------------------------------------------------------------------------
extern "C" void kernel_launch(void* const* d_in, const int* in_sizes, int n_in,
                              void* d_out, int out_size)
{
    const float* x   = (const float*)d_in[0];
    const float* dom = (const float*)d_in[1];
    const float* Wq  = (const float*)d_in[2];
    const float* bq  = (const float*)d_in[3];
    const float* Wk  = (const float*)d_in[4];
    const float* bk  = (const float*)d_in[5];
    const float* Wv  = (const float*)d_in[6];
    const float* bv  = (const float*)d_in[7];
    float* out = (float*)d_out;

    cudaFuncSetAttribute(proj_gemm_kernel,
                         cudaFuncAttributeMaxDynamicSharedMemorySize, SMEM_PJ);
    cudaFuncSetAttribute(gemm1_kernel,
                         cudaFuncAttributeMaxDynamicSharedMemorySize, SMEM_GB);
    cudaFuncSetAttribute(gemm2_kernel,
                         cudaFuncAttributeMaxDynamicSharedMemorySize, SMEM_GB);

    presplit_kernel<<<(NQ * DDIM / 4) / 256, 256>>>(x, dom, Wq, Wk, Wv);

    // q, k, vt projections on tensor cores (z: 0=q, 1=k, 2=vt)
    proj_gemm_kernel<<<dim3(64, 4, 3), 256, SMEM_PJ>>>(bq, bk, bv);

    // P = exp(q k^T)
    gemm1_kernel<<<dim3(NKV / 128, NQ / 128), 256, SMEM_GB>>>();

    lred_kernel<<<NQ / 256, 256>>>();

    // O = (P V) * linv
    gemm2_kernel<<<dim3(DDIM / 128, NQ / 128), 256, SMEM_GB>>>(out);
}